// round 1
// baseline (speedup 1.0000x reference)
#include <cuda_runtime.h>
#include <math.h>

#define D_MODEL 1024
#define NH 16
#define DK 64
#define BATCH 4
#define SEQ 2048
#define M_TOT (BATCH * SEQ)   // 8192

// ---------------------------------------------------------------------------
// Scratch (device globals; no runtime allocation allowed)
// ---------------------------------------------------------------------------
__device__ float g_q [(size_t)M_TOT * D_MODEL];   // [b,h,s,dk]
__device__ float g_k [(size_t)M_TOT * D_MODEL];   // [b,h,s,dk]
__device__ float g_v [(size_t)M_TOT * D_MODEL];   // [b,h,s,dk]
__device__ float g_ao[(size_t)M_TOT * D_MODEL];   // [b,s,h*dk] = [8192,1024]

// ---------------------------------------------------------------------------
// SGEMM: C[M=8192, N=1024] = A[8192,1024] @ W[1024,1024] + bias
// 128x128 tile, BK=16, 256 threads, 8x8 per thread.
// mode 0: scatter into head-major [b,h,s,dk]; mode 1: plain row-major out.
// ---------------------------------------------------------------------------
__global__ __launch_bounds__(256) void gemm_kernel(
    const float* __restrict__ A, const float* __restrict__ W,
    const float* __restrict__ bias, float* __restrict__ out, int mode)
{
    __shared__ float As[16][128];
    __shared__ float Bs[16][128];

    const int tid = threadIdx.x;
    const int bm = blockIdx.y * 128;
    const int bn = blockIdx.x * 128;
    const int tx = tid & 15;     // 16 col-threads
    const int ty = tid >> 4;     // 16 row-threads

    float acc[8][8];
#pragma unroll
    for (int i = 0; i < 8; i++)
#pragma unroll
        for (int j = 0; j < 8; j++) acc[i][j] = 0.f;

    for (int k0 = 0; k0 < D_MODEL; k0 += 16) {
        // Load A tile (transposed into As[k][m]) and B tile (Bs[k][n]); float4 each.
#pragma unroll
        for (int i = 0; i < 2; i++) {
            int idx = tid + i * 256;          // 0..511
            int m   = idx >> 2;               // 0..127
            int ka  = (idx & 3) << 2;         // 0,4,8,12
            float4 t = *(const float4*)(A + (size_t)(bm + m) * D_MODEL + k0 + ka);
            As[ka + 0][m] = t.x; As[ka + 1][m] = t.y;
            As[ka + 2][m] = t.z; As[ka + 3][m] = t.w;

            int kb = idx >> 5;                // 0..15
            int n  = (idx & 31) << 2;         // 0..124
            *(float4*)&Bs[kb][n] =
                *(const float4*)(W + (size_t)(k0 + kb) * D_MODEL + bn + n);
        }
        __syncthreads();

#pragma unroll
        for (int kk = 0; kk < 16; kk++) {
            float a[8], b[8];
#pragma unroll
            for (int i = 0; i < 8; i++) a[i] = As[kk][ty * 8 + i];
#pragma unroll
            for (int j = 0; j < 8; j++) b[j] = Bs[kk][tx * 8 + j];
#pragma unroll
            for (int i = 0; i < 8; i++)
#pragma unroll
                for (int j = 0; j < 8; j++) acc[i][j] += a[i] * b[j];
        }
        __syncthreads();
    }

    // Epilogue: + bias, layout per mode.
#pragma unroll
    for (int i = 0; i < 8; i++) {
        int m = bm + ty * 8 + i;
        if (mode == 0) {
            int b_ = m >> 11;            // m / 2048
            int s  = m & 2047;
#pragma unroll
            for (int j = 0; j < 8; j++) {
                int n  = bn + tx * 8 + j;
                int h  = n >> 6;
                int dd = n & 63;
                out[(((size_t)(b_ * NH + h)) * SEQ + s) * DK + dd] = acc[i][j] + bias[n];
            }
        } else {
#pragma unroll
            for (int j = 0; j < 8; j++) {
                int n = bn + tx * 8 + j;
                out[(size_t)m * D_MODEL + n] = acc[i][j] + bias[n];
            }
        }
    }
}

// ---------------------------------------------------------------------------
// Flash attention (fp32, online softmax).
// Block: 64 queries of one (b,h); loops over 32 key tiles of 64.
// 256 threads; each thread owns a 4x4 micro-tile of S / O.
// Smem: Qs,Ks,Vs,Ss each [64][65] + m/l/alpha rows = 67,328 B dynamic.
// ---------------------------------------------------------------------------
__global__ __launch_bounds__(256) void attn_kernel(
    const float* __restrict__ q, const float* __restrict__ k,
    const float* __restrict__ v, float* __restrict__ o)
{
    extern __shared__ float sm[];
    float* Qs   = sm;                 // [64][65]
    float* Ks   = Qs + 64 * 65;       // [64][65]
    float* Vs   = Ks + 64 * 65;       // [64][65]
    float* Ss   = Vs + 64 * 65;       // [64][65]
    float* mrow = Ss + 64 * 65;       // [64]
    float* lrow = mrow + 64;          // [64]
    float* arow = lrow + 64;          // [64]

    const int bh  = blockIdx.y;       // 0..63  (b*16 + h)
    const int q0  = blockIdx.x * 64;
    const int tid = threadIdx.x;
    const int tx  = tid & 15;
    const int ty  = tid >> 4;
    const int r0  = ty * 4;           // query rows owned
    const int c0  = tx * 4;           // key cols / dk cols owned

    const float* Qg = q + ((size_t)bh * SEQ + q0) * DK;
    const float* Kg = k + (size_t)bh * SEQ * DK;
    const float* Vg = v + (size_t)bh * SEQ * DK;

    // Load Q tile
#pragma unroll
    for (int i = 0; i < 4; i++) {
        int idx = tid + i * 256;      // float4 index 0..1023
        int r   = idx >> 4;
        int c   = (idx & 15) << 2;
        float4 t = *(const float4*)(Qg + r * DK + c);
        float* d = &Qs[r * 65 + c];
        d[0] = t.x; d[1] = t.y; d[2] = t.z; d[3] = t.w;
    }
    if (tid < 64) { mrow[tid] = -3.0e38f; lrow[tid] = 0.f; }

    float O[4][4];
#pragma unroll
    for (int i = 0; i < 4; i++)
#pragma unroll
        for (int j = 0; j < 4; j++) O[i][j] = 0.f;

    for (int kt = 0; kt < SEQ / 64; kt++) {
        // Load K,V tiles [64][64]
#pragma unroll
        for (int i = 0; i < 4; i++) {
            int idx = tid + i * 256;
            int r   = idx >> 4;
            int c   = (idx & 15) << 2;
            float4 tk = *(const float4*)(Kg + (size_t)(kt * 64 + r) * DK + c);
            float4 tv = *(const float4*)(Vg + (size_t)(kt * 64 + r) * DK + c);
            float* dk_ = &Ks[r * 65 + c];
            dk_[0] = tk.x; dk_[1] = tk.y; dk_[2] = tk.z; dk_[3] = tk.w;
            float* dv_ = &Vs[r * 65 + c];
            dv_[0] = tv.x; dv_[1] = tv.y; dv_[2] = tv.z; dv_[3] = tv.w;
        }
        __syncthreads();

        // S = (Q @ K^T) * 1/sqrt(dk)
        float sacc[4][4];
#pragma unroll
        for (int i = 0; i < 4; i++)
#pragma unroll
            for (int j = 0; j < 4; j++) sacc[i][j] = 0.f;
#pragma unroll 8
        for (int d = 0; d < 64; d++) {
            float a[4], b[4];
#pragma unroll
            for (int i = 0; i < 4; i++) a[i] = Qs[(r0 + i) * 65 + d];
#pragma unroll
            for (int j = 0; j < 4; j++) b[j] = Ks[(c0 + j) * 65 + d];
#pragma unroll
            for (int i = 0; i < 4; i++)
#pragma unroll
                for (int j = 0; j < 4; j++) sacc[i][j] += a[i] * b[j];
        }
#pragma unroll
        for (int i = 0; i < 4; i++)
#pragma unroll
            for (int j = 0; j < 4; j++)
                Ss[(r0 + i) * 65 + c0 + j] = sacc[i][j] * 0.125f;
        __syncthreads();

        // Online softmax row update: 4 threads per row, 16 cols each.
        {
            int r  = tid >> 2;
            int qq = tid & 3;
            float* row = &Ss[r * 65 + qq * 16];
            float mx = -3.0e38f;
#pragma unroll
            for (int c = 0; c < 16; c++) mx = fmaxf(mx, row[c]);
            mx = fmaxf(mx, __shfl_xor_sync(0xffffffffu, mx, 1));
            mx = fmaxf(mx, __shfl_xor_sync(0xffffffffu, mx, 2));
            float mold = mrow[r];
            float mnew = fmaxf(mold, mx);
            float al   = __expf(mold - mnew);
            float sum  = 0.f;
#pragma unroll
            for (int c = 0; c < 16; c++) {
                float p = __expf(row[c] - mnew);
                row[c] = p;
                sum += p;
            }
            sum += __shfl_xor_sync(0xffffffffu, sum, 1);
            sum += __shfl_xor_sync(0xffffffffu, sum, 2);
            if (qq == 0) {
                mrow[r] = mnew;
                arow[r] = al;
                lrow[r] = lrow[r] * al + sum;
            }
        }
        __syncthreads();

        // O = O*alpha + P @ V
        float av[4];
#pragma unroll
        for (int i = 0; i < 4; i++) av[i] = arow[r0 + i];
#pragma unroll
        for (int i = 0; i < 4; i++)
#pragma unroll
            for (int j = 0; j < 4; j++) O[i][j] *= av[i];
#pragma unroll 8
        for (int d = 0; d < 64; d++) {
            float a[4], b[4];
#pragma unroll
            for (int i = 0; i < 4; i++) a[i] = Ss[(r0 + i) * 65 + d];
#pragma unroll
            for (int j = 0; j < 4; j++) b[j] = Vs[d * 65 + c0 + j];
#pragma unroll
            for (int i = 0; i < 4; i++)
#pragma unroll
                for (int j = 0; j < 4; j++) O[i][j] += a[i] * b[j];
        }
        __syncthreads();
    }

    // Epilogue: divide by l, write [b,s,h*dk]
    const int b_ = bh >> 4;
    const int h_ = bh & 15;
#pragma unroll
    for (int i = 0; i < 4; i++) {
        float linv = 1.0f / lrow[r0 + i];
        int s = q0 + r0 + i;
        float* dst = o + ((size_t)(b_ * SEQ + s)) * D_MODEL + h_ * DK + c0;
#pragma unroll
        for (int j = 0; j < 4; j++) dst[j] = O[i][j] * linv;
    }
}

// ---------------------------------------------------------------------------
// Launch
// ---------------------------------------------------------------------------
extern "C" void kernel_launch(void* const* d_in, const int* in_sizes, int n_in,
                              void* d_out, int out_size)
{
    const float* x  = (const float*)d_in[0];
    const float* Wq = (const float*)d_in[1];
    const float* bq = (const float*)d_in[2];
    const float* Wk = (const float*)d_in[3];
    const float* bk = (const float*)d_in[4];
    const float* Wv = (const float*)d_in[5];
    const float* bv = (const float*)d_in[6];
    const float* Wo = (const float*)d_in[7];
    const float* bo = (const float*)d_in[8];
    float* out = (float*)d_out;

    float *pq, *pk, *pv, *pao;
    cudaGetSymbolAddress((void**)&pq,  g_q);
    cudaGetSymbolAddress((void**)&pk,  g_k);
    cudaGetSymbolAddress((void**)&pv,  g_v);
    cudaGetSymbolAddress((void**)&pao, g_ao);

    dim3 gg(D_MODEL / 128, M_TOT / 128);   // (8, 64)
    gemm_kernel<<<gg, 256>>>(x, Wq, bq, pq, 0);
    gemm_kernel<<<gg, 256>>>(x, Wk, bk, pk, 0);
    gemm_kernel<<<gg, 256>>>(x, Wv, bv, pv, 0);

    size_t smem = (size_t)(4 * 64 * 65 + 3 * 64) * sizeof(float);  // 67,328 B
    cudaFuncSetAttribute(attn_kernel,
                         cudaFuncAttributeMaxDynamicSharedMemorySize, (int)smem);
    attn_kernel<<<dim3(SEQ / 64, BATCH * NH), 256, smem>>>(pq, pk, pv, pao);

    gemm_kernel<<<gg, 256>>>(pao, Wo, bo, out, 1);
}

// round 2
// speedup vs baseline: 3.2106x; 3.2106x over previous
#include <cuda_runtime.h>

#define D_MODEL 1024
#define NH 16
#define DK 64
#define BATCH 4
#define SEQ 2048
#define M_TOT (BATCH * SEQ)   // 8192

// ---------------------------------------------------------------------------
// Scratch (device globals; allocation is forbidden)
// ---------------------------------------------------------------------------
__device__ float g_q [(size_t)M_TOT * D_MODEL];   // [b,h,s,dk]
__device__ float g_k [(size_t)M_TOT * D_MODEL];   // [b,h,s,dk]
__device__ float g_v [(size_t)M_TOT * D_MODEL];   // [b,h,s,dk]
__device__ float g_ao[(size_t)M_TOT * D_MODEL];   // [b,s,h*dk]

// ---------------------------------------------------------------------------
// tf32 helpers
// ---------------------------------------------------------------------------
__device__ __forceinline__ unsigned f2t(float f) {
    unsigned u;
    asm("cvt.rna.tf32.f32 %0, %1;" : "=r"(u) : "f"(f));
    return u;
}

__device__ __forceinline__ void mma8(float c[4],
    unsigned a0, unsigned a1, unsigned a2, unsigned a3,
    unsigned b0, unsigned b1)
{
    asm volatile(
        "mma.sync.aligned.m16n8k8.row.col.f32.tf32.tf32.f32 "
        "{%0,%1,%2,%3}, {%4,%5,%6,%7}, {%8,%9}, {%0,%1,%2,%3};\n"
        : "+f"(c[0]), "+f"(c[1]), "+f"(c[2]), "+f"(c[3])
        : "r"(a0), "r"(a1), "r"(a2), "r"(a3), "r"(b0), "r"(b1));
}

// ---------------------------------------------------------------------------
// tf32 tensor-core GEMM: C[8192,1024] = A @ W + bias
// 128x128x32 block tile, 256 threads (8 warps, 2x4 of 64x32 warp tiles).
// mode 0: scatter into [b,h,s,dk]; mode 1: row-major out.
// ---------------------------------------------------------------------------
#define BKG 32

__global__ __launch_bounds__(256) void gemm_tc(
    const float* __restrict__ A, const float* __restrict__ W,
    const float* __restrict__ bias, float* __restrict__ out, int mode)
{
    __shared__ unsigned As[128][BKG + 4];   // [m][k], stride 36
    __shared__ unsigned Bs[BKG][128 + 4];   // [k][n], stride 132

    const int tid  = threadIdx.x;
    const int lane = tid & 31;
    const int wid  = tid >> 5;
    const int g    = lane >> 2;     // group id 0..7
    const int qd   = lane & 3;      // thread-in-group 0..3
    const int wm   = (wid >> 2) * 64;
    const int wn   = (wid & 3) * 32;
    const int bm   = blockIdx.y * 128;
    const int bn   = blockIdx.x * 128;

    float c[4][4][4];
#pragma unroll
    for (int mt = 0; mt < 4; mt++)
#pragma unroll
        for (int nt = 0; nt < 4; nt++)
#pragma unroll
            for (int i = 0; i < 4; i++) c[mt][nt][i] = 0.f;

    float4 ra[4], rb[4];

    // prologue load of k0 = 0
#pragma unroll
    for (int i = 0; i < 4; i++) {
        int idx = tid + i * 256;
        int m = idx >> 3, kc = (idx & 7) << 2;
        ra[i] = *(const float4*)(A + (size_t)(bm + m) * D_MODEL + kc);
        int kb = idx >> 5, n = (idx & 31) << 2;
        rb[i] = *(const float4*)(W + (size_t)kb * D_MODEL + bn + n);
    }
#pragma unroll
    for (int i = 0; i < 4; i++) {
        int idx = tid + i * 256;
        int m = idx >> 3, kc = (idx & 7) << 2;
        As[m][kc + 0] = f2t(ra[i].x); As[m][kc + 1] = f2t(ra[i].y);
        As[m][kc + 2] = f2t(ra[i].z); As[m][kc + 3] = f2t(ra[i].w);
        int kb = idx >> 5, n = (idx & 31) << 2;
        Bs[kb][n + 0] = f2t(rb[i].x); Bs[kb][n + 1] = f2t(rb[i].y);
        Bs[kb][n + 2] = f2t(rb[i].z); Bs[kb][n + 3] = f2t(rb[i].w);
    }
    __syncthreads();

    for (int k0 = 0; k0 < D_MODEL; k0 += BKG) {
        const bool more = (k0 + BKG) < D_MODEL;
        if (more) {
#pragma unroll
            for (int i = 0; i < 4; i++) {
                int idx = tid + i * 256;
                int m = idx >> 3, kc = (idx & 7) << 2;
                ra[i] = *(const float4*)(A + (size_t)(bm + m) * D_MODEL + k0 + BKG + kc);
                int kb = idx >> 5, n = (idx & 31) << 2;
                rb[i] = *(const float4*)(W + (size_t)(k0 + BKG + kb) * D_MODEL + bn + n);
            }
        }
#pragma unroll
        for (int kk = 0; kk < 4; kk++) {
            unsigned a[4][4], b[4][2];
#pragma unroll
            for (int mt = 0; mt < 4; mt++) {
                int r = wm + mt * 16;
                a[mt][0] = As[r + g    ][kk * 8 + qd];
                a[mt][1] = As[r + g + 8][kk * 8 + qd];
                a[mt][2] = As[r + g    ][kk * 8 + qd + 4];
                a[mt][3] = As[r + g + 8][kk * 8 + qd + 4];
            }
#pragma unroll
            for (int nt = 0; nt < 4; nt++) {
                int cn = wn + nt * 8 + g;
                b[nt][0] = Bs[kk * 8 + qd    ][cn];
                b[nt][1] = Bs[kk * 8 + qd + 4][cn];
            }
#pragma unroll
            for (int mt = 0; mt < 4; mt++)
#pragma unroll
                for (int nt = 0; nt < 4; nt++)
                    mma8(c[mt][nt], a[mt][0], a[mt][1], a[mt][2], a[mt][3],
                         b[nt][0], b[nt][1]);
        }
        __syncthreads();
        if (more) {
#pragma unroll
            for (int i = 0; i < 4; i++) {
                int idx = tid + i * 256;
                int m = idx >> 3, kc = (idx & 7) << 2;
                As[m][kc + 0] = f2t(ra[i].x); As[m][kc + 1] = f2t(ra[i].y);
                As[m][kc + 2] = f2t(ra[i].z); As[m][kc + 3] = f2t(ra[i].w);
                int kb = idx >> 5, n = (idx & 31) << 2;
                Bs[kb][n + 0] = f2t(rb[i].x); Bs[kb][n + 1] = f2t(rb[i].y);
                Bs[kb][n + 2] = f2t(rb[i].z); Bs[kb][n + 3] = f2t(rb[i].w);
            }
            __syncthreads();
        }
    }

    // epilogue
#pragma unroll
    for (int mt = 0; mt < 4; mt++) {
        int r0 = bm + wm + mt * 16 + g;
        int r1 = r0 + 8;
#pragma unroll
        for (int nt = 0; nt < 4; nt++) {
            int n0 = bn + wn + nt * 8 + 2 * qd;
            float bb0 = bias[n0], bb1 = bias[n0 + 1];
            float v0 = c[mt][nt][0] + bb0, v1 = c[mt][nt][1] + bb1;
            float v2 = c[mt][nt][2] + bb0, v3 = c[mt][nt][3] + bb1;
            if (mode == 0) {
                int h = n0 >> 6, dd = n0 & 63;
                int b0_ = r0 >> 11, s0 = r0 & 2047;
                int b1_ = r1 >> 11, s1 = r1 & 2047;
                float* p0 = out + (((size_t)(b0_ * NH + h)) * SEQ + s0) * DK + dd;
                float* p1 = out + (((size_t)(b1_ * NH + h)) * SEQ + s1) * DK + dd;
                p0[0] = v0; p0[1] = v1;
                p1[0] = v2; p1[1] = v3;
            } else {
                float* p0 = out + (size_t)r0 * D_MODEL + n0;
                float* p1 = out + (size_t)r1 * D_MODEL + n0;
                p0[0] = v0; p0[1] = v1;
                p1[0] = v2; p1[1] = v3;
            }
        }
    }
}

// ---------------------------------------------------------------------------
// Flash attention with tf32 tensor cores.
// Block: 128 queries of one (b,h); 256 threads = 8 warps x 16 q-rows.
// Q fragments register-resident; K tile as B-frags; V stored transposed.
// Smem: Ks[64][68] + Vt[64][68] + Ps[128][68] (Ps doubles as Q staging).
// ---------------------------------------------------------------------------
#define BQ 128

__global__ __launch_bounds__(256) void attn_tc(
    const float* __restrict__ q, const float* __restrict__ k,
    const float* __restrict__ v, float* __restrict__ o)
{
    extern __shared__ unsigned smu[];
    unsigned (*Ks)[68] = (unsigned(*)[68])(smu);
    unsigned (*Vt)[68] = (unsigned(*)[68])(smu + 64 * 68);
    unsigned (*Ps)[68] = (unsigned(*)[68])(smu + 2 * 64 * 68);

    const int tid  = threadIdx.x;
    const int lane = tid & 31;
    const int wid  = tid >> 5;
    const int g    = lane >> 2;
    const int qd   = lane & 3;
    const int bh   = blockIdx.y;
    const int q0   = blockIdx.x * BQ;
    const int wrow = wid * 16;

    const float* Qg = q + ((size_t)bh * SEQ + q0) * DK;
    const float* Kg = k + (size_t)bh * SEQ * DK;
    const float* Vg = v + (size_t)bh * SEQ * DK;

    // stage Q (x 0.125 folded scale) into Ps, then pick up fragments
#pragma unroll
    for (int i = 0; i < 8; i++) {
        int idx = tid + i * 256;
        int r = idx >> 4, c4 = (idx & 15) << 2;
        float4 t = *(const float4*)(Qg + (size_t)r * DK + c4);
        Ps[r][c4 + 0] = f2t(t.x * 0.125f); Ps[r][c4 + 1] = f2t(t.y * 0.125f);
        Ps[r][c4 + 2] = f2t(t.z * 0.125f); Ps[r][c4 + 3] = f2t(t.w * 0.125f);
    }
    __syncthreads();
    unsigned qf[8][4];
#pragma unroll
    for (int kk = 0; kk < 8; kk++) {
        qf[kk][0] = Ps[wrow + g    ][kk * 8 + qd];
        qf[kk][1] = Ps[wrow + g + 8][kk * 8 + qd];
        qf[kk][2] = Ps[wrow + g    ][kk * 8 + qd + 4];
        qf[kk][3] = Ps[wrow + g + 8][kk * 8 + qd + 4];
    }

    float o_acc[8][4];
#pragma unroll
    for (int nt = 0; nt < 8; nt++)
#pragma unroll
        for (int i = 0; i < 4; i++) o_acc[nt][i] = 0.f;
    float m_lo = -1e30f, m_hi = -1e30f, l_lo = 0.f, l_hi = 0.f;

    for (int kt = 0; kt < SEQ / 64; kt++) {
        __syncthreads();   // previous iter's Ks/Vt reads done
#pragma unroll
        for (int i = 0; i < 4; i++) {
            int idx = tid + i * 256;
            int r = idx >> 4, c4 = (idx & 15) << 2;
            float4 tk = *(const float4*)(Kg + ((size_t)(kt * 64 + r)) * DK + c4);
            Ks[r][c4 + 0] = f2t(tk.x); Ks[r][c4 + 1] = f2t(tk.y);
            Ks[r][c4 + 2] = f2t(tk.z); Ks[r][c4 + 3] = f2t(tk.w);
            float4 tv = *(const float4*)(Vg + ((size_t)(kt * 64 + r)) * DK + c4);
            Vt[c4 + 0][r] = f2t(tv.x); Vt[c4 + 1][r] = f2t(tv.y);
            Vt[c4 + 2][r] = f2t(tv.z); Vt[c4 + 3][r] = f2t(tv.w);
        }
        __syncthreads();

        // S = Q @ K^T (scaled); warp computes 16 x 64
        float s[8][4];
#pragma unroll
        for (int nt = 0; nt < 8; nt++)
#pragma unroll
            for (int i = 0; i < 4; i++) s[nt][i] = 0.f;
#pragma unroll
        for (int kk = 0; kk < 8; kk++) {
#pragma unroll
            for (int nt = 0; nt < 8; nt++) {
                unsigned b0 = Ks[nt * 8 + g][kk * 8 + qd];
                unsigned b1 = Ks[nt * 8 + g][kk * 8 + qd + 4];
                mma8(s[nt], qf[kk][0], qf[kk][1], qf[kk][2], qf[kk][3], b0, b1);
            }
        }

        // online softmax (rows g and g+8 of this warp's 16)
        float mx_lo = -1e30f, mx_hi = -1e30f;
#pragma unroll
        for (int nt = 0; nt < 8; nt++) {
            mx_lo = fmaxf(mx_lo, fmaxf(s[nt][0], s[nt][1]));
            mx_hi = fmaxf(mx_hi, fmaxf(s[nt][2], s[nt][3]));
        }
        mx_lo = fmaxf(mx_lo, __shfl_xor_sync(0xffffffffu, mx_lo, 1));
        mx_lo = fmaxf(mx_lo, __shfl_xor_sync(0xffffffffu, mx_lo, 2));
        mx_hi = fmaxf(mx_hi, __shfl_xor_sync(0xffffffffu, mx_hi, 1));
        mx_hi = fmaxf(mx_hi, __shfl_xor_sync(0xffffffffu, mx_hi, 2));

        float mn_lo = fmaxf(m_lo, mx_lo), mn_hi = fmaxf(m_hi, mx_hi);
        float al_lo = __expf(m_lo - mn_lo), al_hi = __expf(m_hi - mn_hi);
        m_lo = mn_lo; m_hi = mn_hi;

        float sum_lo = 0.f, sum_hi = 0.f;
#pragma unroll
        for (int nt = 0; nt < 8; nt++) {
            float p0 = __expf(s[nt][0] - mn_lo);
            float p1 = __expf(s[nt][1] - mn_lo);
            float p2 = __expf(s[nt][2] - mn_hi);
            float p3 = __expf(s[nt][3] - mn_hi);
            sum_lo += p0 + p1; sum_hi += p2 + p3;
            Ps[wrow + g    ][nt * 8 + 2 * qd    ] = f2t(p0);
            Ps[wrow + g    ][nt * 8 + 2 * qd + 1] = f2t(p1);
            Ps[wrow + g + 8][nt * 8 + 2 * qd    ] = f2t(p2);
            Ps[wrow + g + 8][nt * 8 + 2 * qd + 1] = f2t(p3);
        }
        sum_lo += __shfl_xor_sync(0xffffffffu, sum_lo, 1);
        sum_lo += __shfl_xor_sync(0xffffffffu, sum_lo, 2);
        sum_hi += __shfl_xor_sync(0xffffffffu, sum_hi, 1);
        sum_hi += __shfl_xor_sync(0xffffffffu, sum_hi, 2);
        l_lo = l_lo * al_lo + sum_lo;
        l_hi = l_hi * al_hi + sum_hi;

#pragma unroll
        for (int nt = 0; nt < 8; nt++) {
            o_acc[nt][0] *= al_lo; o_acc[nt][1] *= al_lo;
            o_acc[nt][2] *= al_hi; o_acc[nt][3] *= al_hi;
        }
        __syncwarp();

        // O += P @ V  (A frags from warp-private Ps rows, B from Vt)
#pragma unroll
        for (int kk = 0; kk < 8; kk++) {
            unsigned a0 = Ps[wrow + g    ][kk * 8 + qd];
            unsigned a1 = Ps[wrow + g + 8][kk * 8 + qd];
            unsigned a2 = Ps[wrow + g    ][kk * 8 + qd + 4];
            unsigned a3 = Ps[wrow + g + 8][kk * 8 + qd + 4];
#pragma unroll
            for (int nt = 0; nt < 8; nt++) {
                unsigned b0 = Vt[nt * 8 + g][kk * 8 + qd];
                unsigned b1 = Vt[nt * 8 + g][kk * 8 + qd + 4];
                mma8(o_acc[nt], a0, a1, a2, a3, b0, b1);
            }
        }
    }

    // epilogue: normalize + write [b,s,h*dk]
    const float il_lo = 1.f / l_lo, il_hi = 1.f / l_hi;
    const int b_ = bh >> 4, h_ = bh & 15;
    const int s_lo = q0 + wrow + g, s_hi = s_lo + 8;
    float* dst_lo = o + ((size_t)(b_ * SEQ + s_lo)) * D_MODEL + h_ * DK;
    float* dst_hi = o + ((size_t)(b_ * SEQ + s_hi)) * D_MODEL + h_ * DK;
#pragma unroll
    for (int nt = 0; nt < 8; nt++) {
        int n0 = nt * 8 + 2 * qd;
        dst_lo[n0] = o_acc[nt][0] * il_lo; dst_lo[n0 + 1] = o_acc[nt][1] * il_lo;
        dst_hi[n0] = o_acc[nt][2] * il_hi; dst_hi[n0 + 1] = o_acc[nt][3] * il_hi;
    }
}

// ---------------------------------------------------------------------------
// Launch
// ---------------------------------------------------------------------------
extern "C" void kernel_launch(void* const* d_in, const int* in_sizes, int n_in,
                              void* d_out, int out_size)
{
    const float* x  = (const float*)d_in[0];
    const float* Wq = (const float*)d_in[1];
    const float* bq = (const float*)d_in[2];
    const float* Wk = (const float*)d_in[3];
    const float* bk = (const float*)d_in[4];
    const float* Wv = (const float*)d_in[5];
    const float* bv = (const float*)d_in[6];
    const float* Wo = (const float*)d_in[7];
    const float* bo = (const float*)d_in[8];
    float* out = (float*)d_out;

    float *pq, *pk, *pv, *pao;
    cudaGetSymbolAddress((void**)&pq,  g_q);
    cudaGetSymbolAddress((void**)&pk,  g_k);
    cudaGetSymbolAddress((void**)&pv,  g_v);
    cudaGetSymbolAddress((void**)&pao, g_ao);

    dim3 gg(D_MODEL / 128, M_TOT / 128);   // (8, 64)
    gemm_tc<<<gg, 256>>>(x, Wq, bq, pq, 0);
    gemm_tc<<<gg, 256>>>(x, Wk, bk, pk, 0);
    gemm_tc<<<gg, 256>>>(x, Wv, bv, pv, 0);

    size_t smem = (size_t)(2 * 64 * 68 + 128 * 68) * sizeof(unsigned);  // 69,632 B
    cudaFuncSetAttribute(attn_tc,
                         cudaFuncAttributeMaxDynamicSharedMemorySize, (int)smem);
    attn_tc<<<dim3(SEQ / BQ, BATCH * NH), 256, smem>>>(pq, pk, pv, pao);

    gemm_tc<<<gg, 256>>>(pao, Wo, bo, out, 1);
}

// round 3
// speedup vs baseline: 3.7754x; 1.1759x over previous
#include <cuda_runtime.h>

#define D_MODEL 1024
#define NH 16
#define DK 64
#define BATCH 4
#define SEQ 2048
#define M_TOT (BATCH * SEQ)   // 8192

// ---------------------------------------------------------------------------
// Scratch (device globals; allocation is forbidden)
// ---------------------------------------------------------------------------
__device__ float g_q [(size_t)M_TOT * D_MODEL];   // [b,h,s,dk]
__device__ float g_k [(size_t)M_TOT * D_MODEL];   // [b,h,s,dk]
__device__ float g_v [(size_t)M_TOT * D_MODEL];   // [b,h,s,dk]
__device__ float g_ao[(size_t)M_TOT * D_MODEL];   // [b,s,h*dk]

// ---------------------------------------------------------------------------
// tf32 / mma / ldmatrix helpers
// ---------------------------------------------------------------------------
__device__ __forceinline__ unsigned f2t(float f) {
    unsigned u;
    asm("cvt.rna.tf32.f32 %0, %1;" : "=r"(u) : "f"(f));
    return u;
}

__device__ __forceinline__ void mma8(float c[4],
    unsigned a0, unsigned a1, unsigned a2, unsigned a3,
    unsigned b0, unsigned b1)
{
    asm volatile(
        "mma.sync.aligned.m16n8k8.row.col.f32.tf32.tf32.f32 "
        "{%0,%1,%2,%3}, {%4,%5,%6,%7}, {%8,%9}, {%0,%1,%2,%3};\n"
        : "+f"(c[0]), "+f"(c[1]), "+f"(c[2]), "+f"(c[3])
        : "r"(a0), "r"(a1), "r"(a2), "r"(a3), "r"(b0), "r"(b1));
}

__device__ __forceinline__ void ldsm4(unsigned& r0, unsigned& r1,
                                      unsigned& r2, unsigned& r3, unsigned addr)
{
    asm volatile("ldmatrix.sync.aligned.m8n8.x4.shared.b16 {%0,%1,%2,%3}, [%4];\n"
        : "=r"(r0), "=r"(r1), "=r"(r2), "=r"(r3) : "r"(addr));
}

// ---------------------------------------------------------------------------
// tf32 tensor-core GEMM: C[8192,1024] = A @ W + bias
// 128x128x32 tile, 256 threads (8 warps = 2x4 of 64x32 warp tiles).
// Fragments via ldmatrix; Bs stored n-major for LDSM B-frags.
// mode 0: scatter into [b,h,s,dk]; mode 1: row-major out.
// ---------------------------------------------------------------------------
#define BKG 32

__global__ __launch_bounds__(256, 2) void gemm_tc(
    const float* __restrict__ A, const float* __restrict__ W,
    const float* __restrict__ bias, float* __restrict__ out, int mode)
{
    __shared__ unsigned As[128][BKG + 4];   // [m][k], stride 36
    __shared__ unsigned Bs[128][BKG + 4];   // [n][k], stride 36 (n-major!)

    const int tid  = threadIdx.x;
    const int lane = tid & 31;
    const int wid  = tid >> 5;
    const int g    = lane >> 2;
    const int qd   = lane & 3;
    const int wm   = (wid >> 2) * 64;
    const int wn   = (wid & 3) * 32;
    const int bm   = blockIdx.y * 128;
    const int bn   = blockIdx.x * 128;

    const unsigned as_u = (unsigned)__cvta_generic_to_shared(&As[0][0]);
    const unsigned bs_u = (unsigned)__cvta_generic_to_shared(&Bs[0][0]);

    // ldmatrix lane addresses (fixed per thread, add kk*8*4 bytes per chunk)
    // A tile mt: row = wm + mt*16 + (lane&15), col = 4*(lane>>4)
    // B tile np: row = wn + np*16 + (lane&7) + 8*(lane>>4), col = 4*((lane>>3)&1)
    const unsigned a_row = (lane & 15);
    const unsigned a_col = 4 * (lane >> 4);
    const unsigned b_row = (lane & 7) + 8 * (lane >> 4);
    const unsigned b_col = 4 * ((lane >> 3) & 1);

    float c[4][4][4];
#pragma unroll
    for (int mt = 0; mt < 4; mt++)
#pragma unroll
        for (int nt = 0; nt < 4; nt++)
#pragma unroll
            for (int i = 0; i < 4; i++) c[mt][nt][i] = 0.f;

    float4 ra[4];
    float  rb[4][4];

    // ---- load indices ----
    // A: idx -> m = idx>>3, kc = (idx&7)*4   (float4 along k)
    // W: idx -> n = idx&127, k4 = (idx>>7)*4 (4 scalar loads along k, transposed store)

    // prologue (k0 = 0)
#pragma unroll
    for (int i = 0; i < 4; i++) {
        int idx = tid + i * 256;
        int m = idx >> 3, kc = (idx & 7) << 2;
        ra[i] = *(const float4*)(A + (size_t)(bm + m) * D_MODEL + kc);
        int n = idx & 127, k4 = (idx >> 7) << 2;
#pragma unroll
        for (int j = 0; j < 4; j++)
            rb[i][j] = W[(size_t)(k4 + j) * D_MODEL + bn + n];
    }
#pragma unroll
    for (int i = 0; i < 4; i++) {
        int idx = tid + i * 256;
        int m = idx >> 3, kc = (idx & 7) << 2;
        *(uint4*)&As[m][kc] =
            make_uint4(f2t(ra[i].x), f2t(ra[i].y), f2t(ra[i].z), f2t(ra[i].w));
        int n = idx & 127, k4 = (idx >> 7) << 2;
        *(uint4*)&Bs[n][k4] =
            make_uint4(f2t(rb[i][0]), f2t(rb[i][1]), f2t(rb[i][2]), f2t(rb[i][3]));
    }
    __syncthreads();

    for (int k0 = 0; k0 < D_MODEL; k0 += BKG) {
        const bool more = (k0 + BKG) < D_MODEL;
        if (more) {
#pragma unroll
            for (int i = 0; i < 4; i++) {
                int idx = tid + i * 256;
                int m = idx >> 3, kc = (idx & 7) << 2;
                ra[i] = *(const float4*)(A + (size_t)(bm + m) * D_MODEL + k0 + BKG + kc);
                int n = idx & 127, k4 = (idx >> 7) << 2;
#pragma unroll
                for (int j = 0; j < 4; j++)
                    rb[i][j] = W[(size_t)(k0 + BKG + k4 + j) * D_MODEL + bn + n];
            }
        }
#pragma unroll
        for (int kk = 0; kk < 4; kk++) {
            unsigned a[4][4], b[2][4];
#pragma unroll
            for (int mt = 0; mt < 4; mt++) {
                unsigned addr = as_u + ((wm + mt * 16 + a_row) * 36 + kk * 8 + a_col) * 4;
                ldsm4(a[mt][0], a[mt][1], a[mt][2], a[mt][3], addr);
            }
#pragma unroll
            for (int np = 0; np < 2; np++) {
                unsigned addr = bs_u + ((wn + np * 16 + b_row) * 36 + kk * 8 + b_col) * 4;
                ldsm4(b[np][0], b[np][1], b[np][2], b[np][3], addr);
            }
#pragma unroll
            for (int mt = 0; mt < 4; mt++)
#pragma unroll
                for (int np = 0; np < 2; np++) {
                    mma8(c[mt][2 * np],     a[mt][0], a[mt][1], a[mt][2], a[mt][3],
                         b[np][0], b[np][1]);
                    mma8(c[mt][2 * np + 1], a[mt][0], a[mt][1], a[mt][2], a[mt][3],
                         b[np][2], b[np][3]);
                }
        }
        __syncthreads();
        if (more) {
#pragma unroll
            for (int i = 0; i < 4; i++) {
                int idx = tid + i * 256;
                int m = idx >> 3, kc = (idx & 7) << 2;
                *(uint4*)&As[m][kc] =
                    make_uint4(f2t(ra[i].x), f2t(ra[i].y), f2t(ra[i].z), f2t(ra[i].w));
                int n = idx & 127, k4 = (idx >> 7) << 2;
                *(uint4*)&Bs[n][k4] =
                    make_uint4(f2t(rb[i][0]), f2t(rb[i][1]), f2t(rb[i][2]), f2t(rb[i][3]));
            }
            __syncthreads();
        }
    }

    // epilogue
#pragma unroll
    for (int mt = 0; mt < 4; mt++) {
        int r0 = bm + wm + mt * 16 + g;
        int r1 = r0 + 8;
#pragma unroll
        for (int nt = 0; nt < 4; nt++) {
            int n0 = bn + wn + nt * 8 + 2 * qd;
            float bb0 = bias[n0], bb1 = bias[n0 + 1];
            float v0 = c[mt][nt][0] + bb0, v1 = c[mt][nt][1] + bb1;
            float v2 = c[mt][nt][2] + bb0, v3 = c[mt][nt][3] + bb1;
            if (mode == 0) {
                int h = n0 >> 6, dd = n0 & 63;
                int b0_ = r0 >> 11, s0 = r0 & 2047;
                int b1_ = r1 >> 11, s1 = r1 & 2047;
                float* p0 = out + (((size_t)(b0_ * NH + h)) * SEQ + s0) * DK + dd;
                float* p1 = out + (((size_t)(b1_ * NH + h)) * SEQ + s1) * DK + dd;
                p0[0] = v0; p0[1] = v1;
                p1[0] = v2; p1[1] = v3;
            } else {
                float* p0 = out + (size_t)r0 * D_MODEL + n0;
                float* p1 = out + (size_t)r1 * D_MODEL + n0;
                p0[0] = v0; p0[1] = v1;
                p1[0] = v2; p1[1] = v3;
            }
        }
    }
}

// ---------------------------------------------------------------------------
// Flash attention, tf32 tensor cores, ldmatrix fragments, shuffle P-repack.
// Block: 128 queries of one (b,h); 256 threads = 8 warps x 16 q-rows.
// Smem: Ks[64][68] + Vt[64][68] only (34,816 B) -> 2 CTAs/SM.
// ---------------------------------------------------------------------------
#define BQ 128

__global__ __launch_bounds__(256, 2) void attn_tc(
    const float* __restrict__ q, const float* __restrict__ k,
    const float* __restrict__ v, float* __restrict__ o)
{
    extern __shared__ unsigned smu[];
    unsigned (*Ks)[68] = (unsigned(*)[68])(smu);             // [key][dk]
    unsigned (*Vt)[68] = (unsigned(*)[68])(smu + 64 * 68);   // [dk][key]

    const int tid  = threadIdx.x;
    const int lane = tid & 31;
    const int wid  = tid >> 5;
    const int qd   = lane & 3;
    const int bh   = blockIdx.y;
    const int q0   = blockIdx.x * BQ;
    const int wrow = wid * 16;

    const unsigned sm_u = (unsigned)__cvta_generic_to_shared(smu);
    const unsigned ks_u = sm_u;
    const unsigned vt_u = sm_u + 64 * 68 * 4;

    // ldmatrix lane address components
    const unsigned a_row = (lane & 15);
    const unsigned a_col = 4 * (lane >> 4);
    const unsigned b_row = (lane & 7) + 8 * (lane >> 4);
    const unsigned b_col = 4 * ((lane >> 3) & 1);

    // shuffle-repack sources (C-frag -> A-frag)
    const int srcA = (lane & 28) | (qd >> 1);
    const int srcB = srcA + 2;
    const bool oddq = qd & 1;

    const float* Qg = q + ((size_t)bh * SEQ + q0) * DK;
    const float* Kg = k + (size_t)bh * SEQ * DK;
    const float* Vg = v + (size_t)bh * SEQ * DK;

    // ---- stage Q (x0.125) into smem rows 0..127, pick up fragments ----
#pragma unroll
    for (int i = 0; i < 8; i++) {
        int idx = tid + i * 256;
        int r = idx >> 4, c4 = (idx & 15) << 2;
        float4 t = *(const float4*)(Qg + (size_t)r * DK + c4);
        *(uint4*)(smu + r * 68 + c4) =
            make_uint4(f2t(t.x * 0.125f), f2t(t.y * 0.125f),
                       f2t(t.z * 0.125f), f2t(t.w * 0.125f));
    }
    __syncthreads();
    unsigned qf[8][4];
#pragma unroll
    for (int kk = 0; kk < 8; kk++) {
        unsigned addr = sm_u + ((wrow + a_row) * 68 + kk * 8 + a_col) * 4;
        ldsm4(qf[kk][0], qf[kk][1], qf[kk][2], qf[kk][3], addr);
    }

    float o_acc[8][4];
#pragma unroll
    for (int nt = 0; nt < 8; nt++)
#pragma unroll
        for (int i = 0; i < 4; i++) o_acc[nt][i] = 0.f;
    float m_lo = -1e30f, m_hi = -1e30f, l_lo = 0.f, l_hi = 0.f;

    for (int kt = 0; kt < SEQ / 64; kt++) {
        __syncthreads();   // previous Ks/Vt reads done (also covers Q staging)
#pragma unroll
        for (int i = 0; i < 4; i++) {
            int idx = tid + i * 256;
            // K: row-major tile
            int r = idx >> 4, c4 = (idx & 15) << 2;
            float4 tk = *(const float4*)(Kg + ((size_t)(kt * 64 + r)) * DK + c4);
            *(uint4*)&Ks[r][c4] =
                make_uint4(f2t(tk.x), f2t(tk.y), f2t(tk.z), f2t(tk.w));
            // V: transposed tile, 4 coalesced scalar loads + STS.128
            int n = idx & 63, s4 = (idx >> 6) << 2;
            float v0 = Vg[((size_t)(kt * 64 + s4 + 0)) * DK + n];
            float v1 = Vg[((size_t)(kt * 64 + s4 + 1)) * DK + n];
            float v2 = Vg[((size_t)(kt * 64 + s4 + 2)) * DK + n];
            float v3 = Vg[((size_t)(kt * 64 + s4 + 3)) * DK + n];
            *(uint4*)&Vt[n][s4] = make_uint4(f2t(v0), f2t(v1), f2t(v2), f2t(v3));
        }
        __syncthreads();

        // ---- S = Q @ K^T (scale folded into Q); warp computes 16 x 64 ----
        float s[8][4];
#pragma unroll
        for (int nt = 0; nt < 8; nt++)
#pragma unroll
            for (int i = 0; i < 4; i++) s[nt][i] = 0.f;
#pragma unroll
        for (int kk = 0; kk < 8; kk++) {
#pragma unroll
            for (int np = 0; np < 4; np++) {
                unsigned b0, b1, b2, b3;
                unsigned addr = ks_u + ((np * 16 + b_row) * 68 + kk * 8 + b_col) * 4;
                ldsm4(b0, b1, b2, b3, addr);
                mma8(s[2 * np],     qf[kk][0], qf[kk][1], qf[kk][2], qf[kk][3], b0, b1);
                mma8(s[2 * np + 1], qf[kk][0], qf[kk][1], qf[kk][2], qf[kk][3], b2, b3);
            }
        }

        // ---- online softmax (rows g and g+8) ----
        float mx_lo = -1e30f, mx_hi = -1e30f;
#pragma unroll
        for (int nt = 0; nt < 8; nt++) {
            mx_lo = fmaxf(mx_lo, fmaxf(s[nt][0], s[nt][1]));
            mx_hi = fmaxf(mx_hi, fmaxf(s[nt][2], s[nt][3]));
        }
        mx_lo = fmaxf(mx_lo, __shfl_xor_sync(0xffffffffu, mx_lo, 1));
        mx_lo = fmaxf(mx_lo, __shfl_xor_sync(0xffffffffu, mx_lo, 2));
        mx_hi = fmaxf(mx_hi, __shfl_xor_sync(0xffffffffu, mx_hi, 1));
        mx_hi = fmaxf(mx_hi, __shfl_xor_sync(0xffffffffu, mx_hi, 2));

        float mn_lo = fmaxf(m_lo, mx_lo), mn_hi = fmaxf(m_hi, mx_hi);
        float al_lo = __expf(m_lo - mn_lo), al_hi = __expf(m_hi - mn_hi);
        m_lo = mn_lo; m_hi = mn_hi;

        float sum_lo = 0.f, sum_hi = 0.f;
#pragma unroll
        for (int nt = 0; nt < 8; nt++) {
            float p0 = __expf(s[nt][0] - mn_lo);
            float p1 = __expf(s[nt][1] - mn_lo);
            float p2 = __expf(s[nt][2] - mn_hi);
            float p3 = __expf(s[nt][3] - mn_hi);
            sum_lo += p0 + p1; sum_hi += p2 + p3;
            s[nt][0] = __uint_as_float(f2t(p0));
            s[nt][1] = __uint_as_float(f2t(p1));
            s[nt][2] = __uint_as_float(f2t(p2));
            s[nt][3] = __uint_as_float(f2t(p3));
        }
        sum_lo += __shfl_xor_sync(0xffffffffu, sum_lo, 1);
        sum_lo += __shfl_xor_sync(0xffffffffu, sum_lo, 2);
        sum_hi += __shfl_xor_sync(0xffffffffu, sum_hi, 1);
        sum_hi += __shfl_xor_sync(0xffffffffu, sum_hi, 2);
        l_lo = l_lo * al_lo + sum_lo;
        l_hi = l_hi * al_hi + sum_hi;

#pragma unroll
        for (int nt = 0; nt < 8; nt++) {
            o_acc[nt][0] *= al_lo; o_acc[nt][1] *= al_lo;
            o_acc[nt][2] *= al_hi; o_acc[nt][3] *= al_hi;
        }

        // ---- O += P @ V : A-frags via shuffle repack, B-frags via LDSM ----
#pragma unroll
        for (int kk2 = 0; kk2 < 8; kk2++) {
            float v00 = __shfl_sync(0xffffffffu, s[kk2][0], srcA);
            float v01 = __shfl_sync(0xffffffffu, s[kk2][1], srcA);
            float v02 = __shfl_sync(0xffffffffu, s[kk2][2], srcA);
            float v03 = __shfl_sync(0xffffffffu, s[kk2][3], srcA);
            float w00 = __shfl_sync(0xffffffffu, s[kk2][0], srcB);
            float w01 = __shfl_sync(0xffffffffu, s[kk2][1], srcB);
            float w02 = __shfl_sync(0xffffffffu, s[kk2][2], srcB);
            float w03 = __shfl_sync(0xffffffffu, s[kk2][3], srcB);
            unsigned a0 = __float_as_uint(oddq ? v01 : v00);
            unsigned a1 = __float_as_uint(oddq ? v03 : v02);
            unsigned a2 = __float_as_uint(oddq ? w01 : w00);
            unsigned a3 = __float_as_uint(oddq ? w03 : w02);
#pragma unroll
            for (int np = 0; np < 4; np++) {
                unsigned b0, b1, b2, b3;
                unsigned addr = vt_u + ((np * 16 + b_row) * 68 + kk2 * 8 + b_col) * 4;
                ldsm4(b0, b1, b2, b3, addr);
                mma8(o_acc[2 * np],     a0, a1, a2, a3, b0, b1);
                mma8(o_acc[2 * np + 1], a0, a1, a2, a3, b2, b3);
            }
        }
    }

    // ---- epilogue: normalize + write [b,s,h*dk] ----
    const float il_lo = 1.f / l_lo, il_hi = 1.f / l_hi;
    const int b_ = bh >> 4, h_ = bh & 15;
    const int g  = lane >> 2;
    const int s_lo = q0 + wrow + g, s_hi = s_lo + 8;
    float* dst_lo = o + ((size_t)(b_ * SEQ + s_lo)) * D_MODEL + h_ * DK;
    float* dst_hi = o + ((size_t)(b_ * SEQ + s_hi)) * D_MODEL + h_ * DK;
#pragma unroll
    for (int nt = 0; nt < 8; nt++) {
        int n0 = nt * 8 + 2 * qd;
        dst_lo[n0] = o_acc[nt][0] * il_lo; dst_lo[n0 + 1] = o_acc[nt][1] * il_lo;
        dst_hi[n0] = o_acc[nt][2] * il_hi; dst_hi[n0 + 1] = o_acc[nt][3] * il_hi;
    }
}

// ---------------------------------------------------------------------------
// Launch
// ---------------------------------------------------------------------------
extern "C" void kernel_launch(void* const* d_in, const int* in_sizes, int n_in,
                              void* d_out, int out_size)
{
    const float* x  = (const float*)d_in[0];
    const float* Wq = (const float*)d_in[1];
    const float* bq = (const float*)d_in[2];
    const float* Wk = (const float*)d_in[3];
    const float* bk = (const float*)d_in[4];
    const float* Wv = (const float*)d_in[5];
    const float* bv = (const float*)d_in[6];
    const float* Wo = (const float*)d_in[7];
    const float* bo = (const float*)d_in[8];
    float* out = (float*)d_out;

    float *pq, *pk, *pv, *pao;
    cudaGetSymbolAddress((void**)&pq,  g_q);
    cudaGetSymbolAddress((void**)&pk,  g_k);
    cudaGetSymbolAddress((void**)&pv,  g_v);
    cudaGetSymbolAddress((void**)&pao, g_ao);

    dim3 gg(D_MODEL / 128, M_TOT / 128);   // (8, 64)
    gemm_tc<<<gg, 256>>>(x, Wq, bq, pq, 0);
    gemm_tc<<<gg, 256>>>(x, Wk, bk, pk, 0);
    gemm_tc<<<gg, 256>>>(x, Wv, bv, pv, 0);

    size_t smem = (size_t)(2 * 64 * 68) * sizeof(unsigned);  // 34,816 B
    attn_tc<<<dim3(SEQ / BQ, BATCH * NH), 256, smem>>>(pq, pk, pv, pao);

    gemm_tc<<<gg, 256>>>(pao, Wo, bo, out, 1);
}

// round 4
// speedup vs baseline: 4.4182x; 1.1703x over previous
#include <cuda_runtime.h>
#include <cuda_fp16.h>

#define D_MODEL 1024
#define NH 16
#define DK 64
#define BATCH 4
#define SEQ 2048
#define M_TOT (BATCH * SEQ)   // 8192

// ---------------------------------------------------------------------------
// Scratch (device globals; allocation is forbidden)
// ---------------------------------------------------------------------------
__device__ float g_q [(size_t)M_TOT * D_MODEL];   // [b,h,s,dk]
__device__ float g_k [(size_t)M_TOT * D_MODEL];   // [b,h,s,dk]
__device__ float g_v [(size_t)M_TOT * D_MODEL];   // [b,h,s,dk]
__device__ float g_ao[(size_t)M_TOT * D_MODEL];   // [b,s,h*dk]

// ---------------------------------------------------------------------------
// helpers
// ---------------------------------------------------------------------------
__device__ __forceinline__ unsigned f2t(float f) {
    unsigned u;
    asm("cvt.rna.tf32.f32 %0, %1;" : "=r"(u) : "f"(f));
    return u;
}

__device__ __forceinline__ unsigned packh2(float lo, float hi) {
    __half2 h = __floats2half2_rn(lo, hi);
    return *(unsigned*)&h;
}

__device__ __forceinline__ void mma8(float c[4],
    unsigned a0, unsigned a1, unsigned a2, unsigned a3,
    unsigned b0, unsigned b1)
{
    asm volatile(
        "mma.sync.aligned.m16n8k8.row.col.f32.tf32.tf32.f32 "
        "{%0,%1,%2,%3}, {%4,%5,%6,%7}, {%8,%9}, {%0,%1,%2,%3};\n"
        : "+f"(c[0]), "+f"(c[1]), "+f"(c[2]), "+f"(c[3])
        : "r"(a0), "r"(a1), "r"(a2), "r"(a3), "r"(b0), "r"(b1));
}

__device__ __forceinline__ void mma16h(float c[4],
    unsigned a0, unsigned a1, unsigned a2, unsigned a3,
    unsigned b0, unsigned b1)
{
    asm volatile(
        "mma.sync.aligned.m16n8k16.row.col.f32.f16.f16.f32 "
        "{%0,%1,%2,%3}, {%4,%5,%6,%7}, {%8,%9}, {%0,%1,%2,%3};\n"
        : "+f"(c[0]), "+f"(c[1]), "+f"(c[2]), "+f"(c[3])
        : "r"(a0), "r"(a1), "r"(a2), "r"(a3), "r"(b0), "r"(b1));
}

__device__ __forceinline__ void ldsm4(unsigned& r0, unsigned& r1,
                                      unsigned& r2, unsigned& r3, unsigned addr)
{
    asm volatile("ldmatrix.sync.aligned.m8n8.x4.shared.b16 {%0,%1,%2,%3}, [%4];\n"
        : "=r"(r0), "=r"(r1), "=r"(r2), "=r"(r3) : "r"(addr));
}

// ---------------------------------------------------------------------------
// tf32 GEMM: C[8192,1024] = A @ W + bias
// 128x128 block tile, BK=16, 128 threads (4 warps of 64x64 warp tiles).
// mode 0: scatter into [b,h,s,dk]; mode 1: row-major out.
// ---------------------------------------------------------------------------
#define BKH 16

__global__ __launch_bounds__(128, 2) void gemm_tc(
    const float* __restrict__ A, const float* __restrict__ W,
    const float* __restrict__ bias, float* __restrict__ out, int mode)
{
    __shared__ unsigned As[128][BKH + 4];   // [m][k], stride 20
    __shared__ unsigned Bs[128][BKH + 4];   // [n][k], stride 20

    const int tid  = threadIdx.x;
    const int lane = tid & 31;
    const int wid  = tid >> 5;            // 0..3
    const int g    = lane >> 2;
    const int qd   = lane & 3;
    const int wm   = (wid >> 1) * 64;
    const int wn   = (wid & 1) * 64;
    const int bm   = blockIdx.y * 128;
    const int bn   = blockIdx.x * 128;

    const unsigned as_u = (unsigned)__cvta_generic_to_shared(&As[0][0]);
    const unsigned bs_u = (unsigned)__cvta_generic_to_shared(&Bs[0][0]);

    const unsigned a_row = (lane & 15);
    const unsigned a_col = 4 * (lane >> 4);
    const unsigned b_row = (lane & 7) + 8 * (lane >> 4);
    const unsigned b_col = 4 * ((lane >> 3) & 1);

    float c[4][8][4];
#pragma unroll
    for (int mt = 0; mt < 4; mt++)
#pragma unroll
        for (int nt = 0; nt < 8; nt++)
#pragma unroll
            for (int i = 0; i < 4; i++) c[mt][nt][i] = 0.f;

    float4 ra[4];
    float  rb[4][4];

    // A: idx -> m = idx>>2, kc = (idx&3)*4   (float4 along k)
    // W: idx -> n = idx&127, k4 = (idx>>7)*4 (4 scalar loads, transposed store)

    // prologue (k0 = 0)
#pragma unroll
    for (int i = 0; i < 4; i++) {
        int idx = tid + i * 128;
        int m = idx >> 2, kc = (idx & 3) << 2;
        ra[i] = *(const float4*)(A + (size_t)(bm + m) * D_MODEL + kc);
        int n = idx & 127, k4 = (idx >> 7) << 2;
#pragma unroll
        for (int j = 0; j < 4; j++)
            rb[i][j] = W[(size_t)(k4 + j) * D_MODEL + bn + n];
    }
#pragma unroll
    for (int i = 0; i < 4; i++) {
        int idx = tid + i * 128;
        int m = idx >> 2, kc = (idx & 3) << 2;
        *(uint4*)&As[m][kc] =
            make_uint4(f2t(ra[i].x), f2t(ra[i].y), f2t(ra[i].z), f2t(ra[i].w));
        int n = idx & 127, k4 = (idx >> 7) << 2;
        *(uint4*)&Bs[n][k4] =
            make_uint4(f2t(rb[i][0]), f2t(rb[i][1]), f2t(rb[i][2]), f2t(rb[i][3]));
    }
    __syncthreads();

    for (int k0 = 0; k0 < D_MODEL; k0 += BKH) {
        const bool more = (k0 + BKH) < D_MODEL;
        if (more) {
#pragma unroll
            for (int i = 0; i < 4; i++) {
                int idx = tid + i * 128;
                int m = idx >> 2, kc = (idx & 3) << 2;
                ra[i] = *(const float4*)(A + (size_t)(bm + m) * D_MODEL + k0 + BKH + kc);
                int n = idx & 127, k4 = (idx >> 7) << 2;
#pragma unroll
                for (int j = 0; j < 4; j++)
                    rb[i][j] = W[(size_t)(k0 + BKH + k4 + j) * D_MODEL + bn + n];
            }
        }
#pragma unroll
        for (int kk = 0; kk < 2; kk++) {
            unsigned a[4][4], b[4][4];
#pragma unroll
            for (int mt = 0; mt < 4; mt++) {
                unsigned addr = as_u + ((wm + mt * 16 + a_row) * 20 + kk * 8 + a_col) * 4;
                ldsm4(a[mt][0], a[mt][1], a[mt][2], a[mt][3], addr);
            }
#pragma unroll
            for (int np = 0; np < 4; np++) {
                unsigned addr = bs_u + ((wn + np * 16 + b_row) * 20 + kk * 8 + b_col) * 4;
                ldsm4(b[np][0], b[np][1], b[np][2], b[np][3], addr);
            }
#pragma unroll
            for (int mt = 0; mt < 4; mt++)
#pragma unroll
                for (int np = 0; np < 4; np++) {
                    mma8(c[mt][2 * np],     a[mt][0], a[mt][1], a[mt][2], a[mt][3],
                         b[np][0], b[np][1]);
                    mma8(c[mt][2 * np + 1], a[mt][0], a[mt][1], a[mt][2], a[mt][3],
                         b[np][2], b[np][3]);
                }
        }
        __syncthreads();
        if (more) {
#pragma unroll
            for (int i = 0; i < 4; i++) {
                int idx = tid + i * 128;
                int m = idx >> 2, kc = (idx & 3) << 2;
                *(uint4*)&As[m][kc] =
                    make_uint4(f2t(ra[i].x), f2t(ra[i].y), f2t(ra[i].z), f2t(ra[i].w));
                int n = idx & 127, k4 = (idx >> 7) << 2;
                *(uint4*)&Bs[n][k4] =
                    make_uint4(f2t(rb[i][0]), f2t(rb[i][1]), f2t(rb[i][2]), f2t(rb[i][3]));
            }
            __syncthreads();
        }
    }

    // epilogue
#pragma unroll
    for (int mt = 0; mt < 4; mt++) {
        int r0 = bm + wm + mt * 16 + g;
        int r1 = r0 + 8;
#pragma unroll
        for (int nt = 0; nt < 8; nt++) {
            int n0 = bn + wn + nt * 8 + 2 * qd;
            float bb0 = bias[n0], bb1 = bias[n0 + 1];
            float v0 = c[mt][nt][0] + bb0, v1 = c[mt][nt][1] + bb1;
            float v2 = c[mt][nt][2] + bb0, v3 = c[mt][nt][3] + bb1;
            if (mode == 0) {
                int h = n0 >> 6, dd = n0 & 63;
                int b0_ = r0 >> 11, s0 = r0 & 2047;
                int b1_ = r1 >> 11, s1 = r1 & 2047;
                float* p0 = out + (((size_t)(b0_ * NH + h)) * SEQ + s0) * DK + dd;
                float* p1 = out + (((size_t)(b1_ * NH + h)) * SEQ + s1) * DK + dd;
                p0[0] = v0; p0[1] = v1;
                p1[0] = v2; p1[1] = v3;
            } else {
                float* p0 = out + (size_t)r0 * D_MODEL + n0;
                float* p1 = out + (size_t)r1 * D_MODEL + n0;
                p0[0] = v0; p0[1] = v1;
                p1[0] = v2; p1[1] = v3;
            }
        }
    }
}

// ---------------------------------------------------------------------------
// Flash attention: tf32 QK^T, fp16 P@V (same mantissa as tf32 -> no extra err).
// Block: 128 queries of one (b,h); 256 threads = 8 warps x 16 q-rows.
// Smem: Ks[64][68] u32 (17408B) + Vt_h[64][72] half (9216B); Q staged in
// first 34816B at start. Dynamic smem 34816B -> 2 CTAs/SM.
// ---------------------------------------------------------------------------
#define BQ 128
#define VSTR 72

__global__ __launch_bounds__(256, 2) void attn_tc(
    const float* __restrict__ q, const float* __restrict__ k,
    const float* __restrict__ v, float* __restrict__ o)
{
    extern __shared__ unsigned smu[];
    unsigned (*Ks)[68] = (unsigned(*)[68])(smu);        // [key][dk] tf32
    __half* Vt_h = (__half*)(smu + 64 * 68);            // [dk][key] fp16, stride VSTR

    const int tid  = threadIdx.x;
    const int lane = tid & 31;
    const int wid  = tid >> 5;
    const int qd   = lane & 3;
    const int bh   = blockIdx.y;
    const int q0   = blockIdx.x * BQ;
    const int wrow = wid * 16;

    const unsigned sm_u = (unsigned)__cvta_generic_to_shared(smu);
    const unsigned ks_u = sm_u;
    const unsigned vt_u = sm_u + 64 * 68 * 4;

    // ldmatrix lane address components (tf32 K / Q, b16 units = u32 elements)
    const unsigned a_row = (lane & 15);
    const unsigned a_col = 4 * (lane >> 4);
    const unsigned b_row = (lane & 7) + 8 * (lane >> 4);
    const unsigned b_col = 4 * ((lane >> 3) & 1);
    // fp16 V B-frag lane components (half elements)
    const unsigned v_n = (lane & 7) + ((lane >> 4) & 1) * 8;
    const unsigned v_k = ((lane >> 3) & 1) * 8;

    const float* Qg = q + ((size_t)bh * SEQ + q0) * DK;
    const float* Kg = k + (size_t)bh * SEQ * DK;
    const float* Vg = v + (size_t)bh * SEQ * DK;

    // ---- stage Q (x0.125) into smem rows 0..127, pick up fragments ----
#pragma unroll
    for (int i = 0; i < 8; i++) {
        int idx = tid + i * 256;
        int r = idx >> 4, c4 = (idx & 15) << 2;
        float4 t = *(const float4*)(Qg + (size_t)r * DK + c4);
        *(uint4*)(smu + r * 68 + c4) =
            make_uint4(f2t(t.x * 0.125f), f2t(t.y * 0.125f),
                       f2t(t.z * 0.125f), f2t(t.w * 0.125f));
    }
    __syncthreads();
    unsigned qf[8][4];
#pragma unroll
    for (int kk = 0; kk < 8; kk++) {
        unsigned addr = sm_u + ((wrow + a_row) * 68 + kk * 8 + a_col) * 4;
        ldsm4(qf[kk][0], qf[kk][1], qf[kk][2], qf[kk][3], addr);
    }

    float o_acc[8][4];
#pragma unroll
    for (int nt = 0; nt < 8; nt++)
#pragma unroll
        for (int i = 0; i < 4; i++) o_acc[nt][i] = 0.f;
    float m_lo = -1e30f, m_hi = -1e30f, l_lo = 0.f, l_hi = 0.f;

    for (int kt = 0; kt < SEQ / 64; kt++) {
        __syncthreads();   // previous Ks/Vt reads done (also covers Q staging)
#pragma unroll
        for (int i = 0; i < 4; i++) {
            int idx = tid + i * 256;
            // K: row-major tf32 tile
            int r = idx >> 4, c4 = (idx & 15) << 2;
            float4 tk = *(const float4*)(Kg + ((size_t)(kt * 64 + r)) * DK + c4);
            *(uint4*)&Ks[r][c4] =
                make_uint4(f2t(tk.x), f2t(tk.y), f2t(tk.z), f2t(tk.w));
            // V: transposed fp16 tile, 4 coalesced scalar loads
            int n = idx & 63, s4 = (idx >> 6) << 2;
            float v0 = Vg[((size_t)(kt * 64 + s4 + 0)) * DK + n];
            float v1 = Vg[((size_t)(kt * 64 + s4 + 1)) * DK + n];
            float v2 = Vg[((size_t)(kt * 64 + s4 + 2)) * DK + n];
            float v3 = Vg[((size_t)(kt * 64 + s4 + 3)) * DK + n];
            __half* vp = Vt_h + n * VSTR + s4;
            *(__half2*)(vp)     = __floats2half2_rn(v0, v1);
            *(__half2*)(vp + 2) = __floats2half2_rn(v2, v3);
        }
        __syncthreads();

        // ---- S = Q @ K^T (scale folded into Q); warp computes 16 x 64 ----
        float s[8][4];
#pragma unroll
        for (int nt = 0; nt < 8; nt++)
#pragma unroll
            for (int i = 0; i < 4; i++) s[nt][i] = 0.f;
#pragma unroll
        for (int kk = 0; kk < 8; kk++) {
#pragma unroll
            for (int np = 0; np < 4; np++) {
                unsigned b0, b1, b2, b3;
                unsigned addr = ks_u + ((np * 16 + b_row) * 68 + kk * 8 + b_col) * 4;
                ldsm4(b0, b1, b2, b3, addr);
                mma8(s[2 * np],     qf[kk][0], qf[kk][1], qf[kk][2], qf[kk][3], b0, b1);
                mma8(s[2 * np + 1], qf[kk][0], qf[kk][1], qf[kk][2], qf[kk][3], b2, b3);
            }
        }

        // ---- online softmax (rows g and g+8) ----
        float mx_lo = -1e30f, mx_hi = -1e30f;
#pragma unroll
        for (int nt = 0; nt < 8; nt++) {
            mx_lo = fmaxf(mx_lo, fmaxf(s[nt][0], s[nt][1]));
            mx_hi = fmaxf(mx_hi, fmaxf(s[nt][2], s[nt][3]));
        }
        mx_lo = fmaxf(mx_lo, __shfl_xor_sync(0xffffffffu, mx_lo, 1));
        mx_lo = fmaxf(mx_lo, __shfl_xor_sync(0xffffffffu, mx_lo, 2));
        mx_hi = fmaxf(mx_hi, __shfl_xor_sync(0xffffffffu, mx_hi, 1));
        mx_hi = fmaxf(mx_hi, __shfl_xor_sync(0xffffffffu, mx_hi, 2));

        float mn_lo = fmaxf(m_lo, mx_lo), mn_hi = fmaxf(m_hi, mx_hi);
        float al_lo = __expf(m_lo - mn_lo), al_hi = __expf(m_hi - mn_hi);
        m_lo = mn_lo; m_hi = mn_hi;

        float sum_lo = 0.f, sum_hi = 0.f;
#pragma unroll
        for (int nt = 0; nt < 8; nt++) {
            float p0 = __expf(s[nt][0] - mn_lo);
            float p1 = __expf(s[nt][1] - mn_lo);
            float p2 = __expf(s[nt][2] - mn_hi);
            float p3 = __expf(s[nt][3] - mn_hi);
            sum_lo += p0 + p1; sum_hi += p2 + p3;
            s[nt][0] = p0; s[nt][1] = p1; s[nt][2] = p2; s[nt][3] = p3;
        }
        sum_lo += __shfl_xor_sync(0xffffffffu, sum_lo, 1);
        sum_lo += __shfl_xor_sync(0xffffffffu, sum_lo, 2);
        sum_hi += __shfl_xor_sync(0xffffffffu, sum_hi, 1);
        sum_hi += __shfl_xor_sync(0xffffffffu, sum_hi, 2);
        l_lo = l_lo * al_lo + sum_lo;
        l_hi = l_hi * al_hi + sum_hi;

#pragma unroll
        for (int nt = 0; nt < 8; nt++) {
            o_acc[nt][0] *= al_lo; o_acc[nt][1] *= al_lo;
            o_acc[nt][2] *= al_hi; o_acc[nt][3] *= al_hi;
        }

        // ---- O += P @ V : fp16 m16n8k16; P C-frags pack directly to A-frags ----
#pragma unroll
        for (int kk2 = 0; kk2 < 4; kk2++) {
            unsigned a0 = packh2(s[2 * kk2][0],     s[2 * kk2][1]);
            unsigned a1 = packh2(s[2 * kk2][2],     s[2 * kk2][3]);
            unsigned a2 = packh2(s[2 * kk2 + 1][0], s[2 * kk2 + 1][1]);
            unsigned a3 = packh2(s[2 * kk2 + 1][2], s[2 * kk2 + 1][3]);
#pragma unroll
            for (int np = 0; np < 4; np++) {
                unsigned b0, b1, b2, b3;
                unsigned addr = vt_u + ((np * 16 + v_n) * VSTR + kk2 * 16 + v_k) * 2;
                ldsm4(b0, b1, b2, b3, addr);
                mma16h(o_acc[2 * np],     a0, a1, a2, a3, b0, b1);
                mma16h(o_acc[2 * np + 1], a0, a1, a2, a3, b2, b3);
            }
        }
    }

    // ---- epilogue: normalize + write [b,s,h*dk] ----
    const float il_lo = 1.f / l_lo, il_hi = 1.f / l_hi;
    const int b_ = bh >> 4, h_ = bh & 15;
    const int g  = lane >> 2;
    const int s_lo = q0 + wrow + g, s_hi = s_lo + 8;
    float* dst_lo = o + ((size_t)(b_ * SEQ + s_lo)) * D_MODEL + h_ * DK;
    float* dst_hi = o + ((size_t)(b_ * SEQ + s_hi)) * D_MODEL + h_ * DK;
#pragma unroll
    for (int nt = 0; nt < 8; nt++) {
        int n0 = nt * 8 + 2 * qd;
        dst_lo[n0] = o_acc[nt][0] * il_lo; dst_lo[n0 + 1] = o_acc[nt][1] * il_lo;
        dst_hi[n0] = o_acc[nt][2] * il_hi; dst_hi[n0 + 1] = o_acc[nt][3] * il_hi;
    }
}

// ---------------------------------------------------------------------------
// Launch
// ---------------------------------------------------------------------------
extern "C" void kernel_launch(void* const* d_in, const int* in_sizes, int n_in,
                              void* d_out, int out_size)
{
    const float* x  = (const float*)d_in[0];
    const float* Wq = (const float*)d_in[1];
    const float* bq = (const float*)d_in[2];
    const float* Wk = (const float*)d_in[3];
    const float* bk = (const float*)d_in[4];
    const float* Wv = (const float*)d_in[5];
    const float* bv = (const float*)d_in[6];
    const float* Wo = (const float*)d_in[7];
    const float* bo = (const float*)d_in[8];
    float* out = (float*)d_out;

    float *pq, *pk, *pv, *pao;
    cudaGetSymbolAddress((void**)&pq,  g_q);
    cudaGetSymbolAddress((void**)&pk,  g_k);
    cudaGetSymbolAddress((void**)&pv,  g_v);
    cudaGetSymbolAddress((void**)&pao, g_ao);

    dim3 gg(D_MODEL / 128, M_TOT / 128);   // (8, 64)
    gemm_tc<<<gg, 128>>>(x, Wq, bq, pq, 0);
    gemm_tc<<<gg, 128>>>(x, Wk, bk, pk, 0);
    gemm_tc<<<gg, 128>>>(x, Wv, bv, pv, 0);

    size_t smem = (size_t)(128 * 68) * sizeof(unsigned);  // 34,816 B (Q staging max)
    attn_tc<<<dim3(SEQ / BQ, BATCH * NH), 256, smem>>>(pq, pk, pv, pao);

    gemm_tc<<<gg, 128>>>(pao, Wo, bo, out, 1);
}

// round 5
// speedup vs baseline: 5.6343x; 1.2753x over previous
#include <cuda_runtime.h>
#include <cuda_fp16.h>

#define D_MODEL 1024
#define NH 16
#define DK 64
#define BATCH 4
#define SEQ 2048
#define M_TOT (BATCH * SEQ)   // 8192

// ---------------------------------------------------------------------------
// Scratch (device globals; allocation is forbidden)
// ---------------------------------------------------------------------------
__device__ float g_q [(size_t)M_TOT * D_MODEL];   // [b,h,s,dk]
__device__ float g_k [(size_t)M_TOT * D_MODEL];   // [b,h,s,dk]
__device__ float g_v [(size_t)M_TOT * D_MODEL];   // [b,h,s,dk]
__device__ float g_ao[(size_t)M_TOT * D_MODEL];   // [b,s,h*dk]

// ---------------------------------------------------------------------------
// helpers
// ---------------------------------------------------------------------------
__device__ __forceinline__ unsigned packh2(float lo, float hi) {
    __half2 h = __floats2half2_rn(lo, hi);
    return *(unsigned*)&h;
}

__device__ __forceinline__ void mma16h(float c[4],
    unsigned a0, unsigned a1, unsigned a2, unsigned a3,
    unsigned b0, unsigned b1)
{
    asm volatile(
        "mma.sync.aligned.m16n8k16.row.col.f32.f16.f16.f32 "
        "{%0,%1,%2,%3}, {%4,%5,%6,%7}, {%8,%9}, {%0,%1,%2,%3};\n"
        : "+f"(c[0]), "+f"(c[1]), "+f"(c[2]), "+f"(c[3])
        : "r"(a0), "r"(a1), "r"(a2), "r"(a3), "r"(b0), "r"(b1));
}

__device__ __forceinline__ void ldsm4(unsigned& r0, unsigned& r1,
                                      unsigned& r2, unsigned& r3, unsigned addr)
{
    asm volatile("ldmatrix.sync.aligned.m8n8.x4.shared.b16 {%0,%1,%2,%3}, [%4];\n"
        : "=r"(r0), "=r"(r1), "=r"(r2), "=r"(r3) : "r"(addr));
}

// ---------------------------------------------------------------------------
// fp16 GEMM: C[8192,1024] = A @ W + bias  (fp32 in/out, fp16 mma, fp32 accum)
// 128x128 block tile, BK=16, 128 threads (4 warps of 64x64 warp tiles).
// As[m][k] half (stride 24), Bs[n][k] half (stride 24).
// mode 0: scatter into [b,h,s,dk]; mode 1: row-major out.
// ---------------------------------------------------------------------------
#define BKH 16
#define ASTR 24   // halves; 48B row stride -> conflict-free ldsm

__global__ __launch_bounds__(128, 2) void gemm_tc(
    const float* __restrict__ A, const float* __restrict__ W,
    const float* __restrict__ bias, float* __restrict__ out, int mode)
{
    __shared__ __half As[128 * ASTR];
    __shared__ __half Bs[128 * ASTR];

    const int tid  = threadIdx.x;
    const int lane = tid & 31;
    const int wid  = tid >> 5;            // 0..3
    const int g    = lane >> 2;
    const int qd   = lane & 3;
    const int wm   = (wid >> 1) * 64;
    const int wn   = (wid & 1) * 64;
    const int bm   = blockIdx.y * 128;
    const int bn   = blockIdx.x * 128;

    const unsigned as_u = (unsigned)__cvta_generic_to_shared(As);
    const unsigned bs_u = (unsigned)__cvta_generic_to_shared(Bs);

    // fragment lane addressing (halves)
    const unsigned a_row = (lane & 15);
    const unsigned a_col = (lane >> 4) * 8;
    const unsigned b_n   = (lane & 7) + ((lane >> 4) & 1) * 8;
    const unsigned b_k   = ((lane >> 3) & 1) * 8;

    float c[4][8][4];
#pragma unroll
    for (int mt = 0; mt < 4; mt++)
#pragma unroll
        for (int nt = 0; nt < 8; nt++)
#pragma unroll
            for (int i = 0; i < 4; i++) c[mt][nt][i] = 0.f;

    float4 ra[4];
    float  rb[4][4];

    // A: idx -> m = idx>>2, kc = (idx&3)*4   (float4 along k)
    // W: idx -> n = idx&127, k4 = (idx>>7)*4 (4 scalar loads, transposed store)

    // prologue (k0 = 0)
#pragma unroll
    for (int i = 0; i < 4; i++) {
        int idx = tid + i * 128;
        int m = idx >> 2, kc = (idx & 3) << 2;
        ra[i] = *(const float4*)(A + (size_t)(bm + m) * D_MODEL + kc);
        int n = idx & 127, k4 = (idx >> 7) << 2;
#pragma unroll
        for (int j = 0; j < 4; j++)
            rb[i][j] = W[(size_t)(k4 + j) * D_MODEL + bn + n];
    }
#pragma unroll
    for (int i = 0; i < 4; i++) {
        int idx = tid + i * 128;
        int m = idx >> 2, kc = (idx & 3) << 2;
        *(uint2*)&As[m * ASTR + kc] =
            make_uint2(packh2(ra[i].x, ra[i].y), packh2(ra[i].z, ra[i].w));
        int n = idx & 127, k4 = (idx >> 7) << 2;
        *(uint2*)&Bs[n * ASTR + k4] =
            make_uint2(packh2(rb[i][0], rb[i][1]), packh2(rb[i][2], rb[i][3]));
    }
    __syncthreads();

    for (int k0 = 0; k0 < D_MODEL; k0 += BKH) {
        const bool more = (k0 + BKH) < D_MODEL;
        if (more) {
#pragma unroll
            for (int i = 0; i < 4; i++) {
                int idx = tid + i * 128;
                int m = idx >> 2, kc = (idx & 3) << 2;
                ra[i] = *(const float4*)(A + (size_t)(bm + m) * D_MODEL + k0 + BKH + kc);
                int n = idx & 127, k4 = (idx >> 7) << 2;
#pragma unroll
                for (int j = 0; j < 4; j++)
                    rb[i][j] = W[(size_t)(k0 + BKH + k4 + j) * D_MODEL + bn + n];
            }
        }
        // one k16 chunk per iteration
        {
            unsigned a[4][4], b[4][4];
#pragma unroll
            for (int mt = 0; mt < 4; mt++) {
                unsigned addr = as_u + ((wm + mt * 16 + a_row) * ASTR + a_col) * 2;
                ldsm4(a[mt][0], a[mt][1], a[mt][2], a[mt][3], addr);
            }
#pragma unroll
            for (int np = 0; np < 4; np++) {
                unsigned addr = bs_u + ((wn + np * 16 + b_n) * ASTR + b_k) * 2;
                ldsm4(b[np][0], b[np][1], b[np][2], b[np][3], addr);
            }
#pragma unroll
            for (int mt = 0; mt < 4; mt++)
#pragma unroll
                for (int np = 0; np < 4; np++) {
                    mma16h(c[mt][2 * np],     a[mt][0], a[mt][1], a[mt][2], a[mt][3],
                           b[np][0], b[np][1]);
                    mma16h(c[mt][2 * np + 1], a[mt][0], a[mt][1], a[mt][2], a[mt][3],
                           b[np][2], b[np][3]);
                }
        }
        __syncthreads();
        if (more) {
#pragma unroll
            for (int i = 0; i < 4; i++) {
                int idx = tid + i * 128;
                int m = idx >> 2, kc = (idx & 3) << 2;
                *(uint2*)&As[m * ASTR + kc] =
                    make_uint2(packh2(ra[i].x, ra[i].y), packh2(ra[i].z, ra[i].w));
                int n = idx & 127, k4 = (idx >> 7) << 2;
                *(uint2*)&Bs[n * ASTR + k4] =
                    make_uint2(packh2(rb[i][0], rb[i][1]), packh2(rb[i][2], rb[i][3]));
            }
            __syncthreads();
        }
    }

    // epilogue
#pragma unroll
    for (int mt = 0; mt < 4; mt++) {
        int r0 = bm + wm + mt * 16 + g;
        int r1 = r0 + 8;
#pragma unroll
        for (int nt = 0; nt < 8; nt++) {
            int n0 = bn + wn + nt * 8 + 2 * qd;
            float bb0 = bias[n0], bb1 = bias[n0 + 1];
            float v0 = c[mt][nt][0] + bb0, v1 = c[mt][nt][1] + bb1;
            float v2 = c[mt][nt][2] + bb0, v3 = c[mt][nt][3] + bb1;
            if (mode == 0) {
                int h = n0 >> 6, dd = n0 & 63;
                int b0_ = r0 >> 11, s0 = r0 & 2047;
                int b1_ = r1 >> 11, s1 = r1 & 2047;
                float* p0 = out + (((size_t)(b0_ * NH + h)) * SEQ + s0) * DK + dd;
                float* p1 = out + (((size_t)(b1_ * NH + h)) * SEQ + s1) * DK + dd;
                p0[0] = v0; p0[1] = v1;
                p1[0] = v2; p1[1] = v3;
            } else {
                float* p0 = out + (size_t)r0 * D_MODEL + n0;
                float* p1 = out + (size_t)r1 * D_MODEL + n0;
                p0[0] = v0; p0[1] = v1;
                p1[0] = v2; p1[1] = v3;
            }
        }
    }
}

// ---------------------------------------------------------------------------
// Flash attention, all-fp16 mma (fp32 accumulate, fp32 softmax).
// Block: 128 queries of one (b,h); 256 threads = 8 warps x 16 q-rows.
// Smem: Ks[64][72]h (9216B) + Vt[64][72]h (9216B); Q staged over same 18.4KB.
// ---------------------------------------------------------------------------
#define BQ 128
#define KSTR 72   // halves; 144B stride -> conflict-free ldsm

__global__ __launch_bounds__(256, 2) void attn_tc(
    const float* __restrict__ q, const float* __restrict__ k,
    const float* __restrict__ v, float* __restrict__ o)
{
    extern __shared__ __half smh[];
    __half* Ks_h = smh;                   // [key][dk]
    __half* Vt_h = smh + 64 * KSTR;       // [dk][key]

    const int tid  = threadIdx.x;
    const int lane = tid & 31;
    const int wid  = tid >> 5;
    const int qd   = lane & 3;
    const int bh   = blockIdx.y;
    const int q0   = blockIdx.x * BQ;
    const int wrow = wid * 16;

    const unsigned sm_u = (unsigned)__cvta_generic_to_shared(smh);
    const unsigned ks_u = sm_u;
    const unsigned vt_u = sm_u + 64 * KSTR * 2;

    // fragment lane addressing (halves)
    const unsigned a_row = (lane & 15);
    const unsigned a_col = (lane >> 4) * 8;
    const unsigned b_n   = (lane & 7) + ((lane >> 4) & 1) * 8;
    const unsigned b_k   = ((lane >> 3) & 1) * 8;

    const float* Qg = q + ((size_t)bh * SEQ + q0) * DK;
    const float* Kg = k + (size_t)bh * SEQ * DK;
    const float* Vg = v + (size_t)bh * SEQ * DK;

    // ---- stage Q (x0.125) as fp16 into smem rows 0..127, pick up fragments ----
#pragma unroll
    for (int i = 0; i < 8; i++) {
        int idx = tid + i * 256;
        int r = idx >> 4, c4 = (idx & 15) << 2;
        float4 t = *(const float4*)(Qg + (size_t)r * DK + c4);
        *(uint2*)(smh + r * KSTR + c4) =
            make_uint2(packh2(t.x * 0.125f, t.y * 0.125f),
                       packh2(t.z * 0.125f, t.w * 0.125f));
    }
    __syncthreads();
    unsigned qf[4][4];
#pragma unroll
    for (int kk = 0; kk < 4; kk++) {
        unsigned addr = sm_u + ((wrow + a_row) * KSTR + kk * 16 + a_col) * 2;
        ldsm4(qf[kk][0], qf[kk][1], qf[kk][2], qf[kk][3], addr);
    }

    float o_acc[8][4];
#pragma unroll
    for (int nt = 0; nt < 8; nt++)
#pragma unroll
        for (int i = 0; i < 4; i++) o_acc[nt][i] = 0.f;
    float m_lo = -1e30f, m_hi = -1e30f, l_lo = 0.f, l_hi = 0.f;

    for (int kt = 0; kt < SEQ / 64; kt++) {
        __syncthreads();   // previous Ks/Vt reads done (also covers Q staging)
#pragma unroll
        for (int i = 0; i < 4; i++) {
            int idx = tid + i * 256;
            // K: row-major fp16 tile
            int r = idx >> 4, c4 = (idx & 15) << 2;
            float4 tk = *(const float4*)(Kg + ((size_t)(kt * 64 + r)) * DK + c4);
            *(uint2*)(Ks_h + r * KSTR + c4) =
                make_uint2(packh2(tk.x, tk.y), packh2(tk.z, tk.w));
            // V: transposed fp16 tile, 4 coalesced scalar loads
            int n = idx & 63, s4 = (idx >> 6) << 2;
            float v0 = Vg[((size_t)(kt * 64 + s4 + 0)) * DK + n];
            float v1 = Vg[((size_t)(kt * 64 + s4 + 1)) * DK + n];
            float v2 = Vg[((size_t)(kt * 64 + s4 + 2)) * DK + n];
            float v3 = Vg[((size_t)(kt * 64 + s4 + 3)) * DK + n];
            *(uint2*)(Vt_h + n * KSTR + s4) =
                make_uint2(packh2(v0, v1), packh2(v2, v3));
        }
        __syncthreads();

        // ---- S = Q @ K^T (scale folded into Q); warp computes 16 x 64 ----
        float s[8][4];
#pragma unroll
        for (int nt = 0; nt < 8; nt++)
#pragma unroll
            for (int i = 0; i < 4; i++) s[nt][i] = 0.f;
#pragma unroll
        for (int kk = 0; kk < 4; kk++) {
#pragma unroll
            for (int np = 0; np < 4; np++) {
                unsigned b0, b1, b2, b3;
                unsigned addr = ks_u + ((np * 16 + b_n) * KSTR + kk * 16 + b_k) * 2;
                ldsm4(b0, b1, b2, b3, addr);
                mma16h(s[2 * np],     qf[kk][0], qf[kk][1], qf[kk][2], qf[kk][3], b0, b1);
                mma16h(s[2 * np + 1], qf[kk][0], qf[kk][1], qf[kk][2], qf[kk][3], b2, b3);
            }
        }

        // ---- online softmax (rows g and g+8) ----
        float mx_lo = -1e30f, mx_hi = -1e30f;
#pragma unroll
        for (int nt = 0; nt < 8; nt++) {
            mx_lo = fmaxf(mx_lo, fmaxf(s[nt][0], s[nt][1]));
            mx_hi = fmaxf(mx_hi, fmaxf(s[nt][2], s[nt][3]));
        }
        mx_lo = fmaxf(mx_lo, __shfl_xor_sync(0xffffffffu, mx_lo, 1));
        mx_lo = fmaxf(mx_lo, __shfl_xor_sync(0xffffffffu, mx_lo, 2));
        mx_hi = fmaxf(mx_hi, __shfl_xor_sync(0xffffffffu, mx_hi, 1));
        mx_hi = fmaxf(mx_hi, __shfl_xor_sync(0xffffffffu, mx_hi, 2));

        float mn_lo = fmaxf(m_lo, mx_lo), mn_hi = fmaxf(m_hi, mx_hi);
        float al_lo = __expf(m_lo - mn_lo), al_hi = __expf(m_hi - mn_hi);
        m_lo = mn_lo; m_hi = mn_hi;

        float sum_lo = 0.f, sum_hi = 0.f;
#pragma unroll
        for (int nt = 0; nt < 8; nt++) {
            float p0 = __expf(s[nt][0] - mn_lo);
            float p1 = __expf(s[nt][1] - mn_lo);
            float p2 = __expf(s[nt][2] - mn_hi);
            float p3 = __expf(s[nt][3] - mn_hi);
            sum_lo += p0 + p1; sum_hi += p2 + p3;
            s[nt][0] = p0; s[nt][1] = p1; s[nt][2] = p2; s[nt][3] = p3;
        }
        sum_lo += __shfl_xor_sync(0xffffffffu, sum_lo, 1);
        sum_lo += __shfl_xor_sync(0xffffffffu, sum_lo, 2);
        sum_hi += __shfl_xor_sync(0xffffffffu, sum_hi, 1);
        sum_hi += __shfl_xor_sync(0xffffffffu, sum_hi, 2);
        l_lo = l_lo * al_lo + sum_lo;
        l_hi = l_hi * al_hi + sum_hi;

#pragma unroll
        for (int nt = 0; nt < 8; nt++) {
            o_acc[nt][0] *= al_lo; o_acc[nt][1] *= al_lo;
            o_acc[nt][2] *= al_hi; o_acc[nt][3] *= al_hi;
        }

        // ---- O += P @ V : fp16 m16n8k16; P C-frags pack directly to A-frags ----
#pragma unroll
        for (int kk2 = 0; kk2 < 4; kk2++) {
            unsigned a0 = packh2(s[2 * kk2][0],     s[2 * kk2][1]);
            unsigned a1 = packh2(s[2 * kk2][2],     s[2 * kk2][3]);
            unsigned a2 = packh2(s[2 * kk2 + 1][0], s[2 * kk2 + 1][1]);
            unsigned a3 = packh2(s[2 * kk2 + 1][2], s[2 * kk2 + 1][3]);
#pragma unroll
            for (int np = 0; np < 4; np++) {
                unsigned b0, b1, b2, b3;
                unsigned addr = vt_u + ((np * 16 + b_n) * KSTR + kk2 * 16 + b_k) * 2;
                ldsm4(b0, b1, b2, b3, addr);
                mma16h(o_acc[2 * np],     a0, a1, a2, a3, b0, b1);
                mma16h(o_acc[2 * np + 1], a0, a1, a2, a3, b2, b3);
            }
        }
    }

    // ---- epilogue: normalize + write [b,s,h*dk] ----
    const float il_lo = 1.f / l_lo, il_hi = 1.f / l_hi;
    const int b_ = bh >> 4, h_ = bh & 15;
    const int g  = lane >> 2;
    const int s_lo = q0 + wrow + g, s_hi = s_lo + 8;
    float* dst_lo = o + ((size_t)(b_ * SEQ + s_lo)) * D_MODEL + h_ * DK;
    float* dst_hi = o + ((size_t)(b_ * SEQ + s_hi)) * D_MODEL + h_ * DK;
#pragma unroll
    for (int nt = 0; nt < 8; nt++) {
        int n0 = nt * 8 + 2 * qd;
        dst_lo[n0] = o_acc[nt][0] * il_lo; dst_lo[n0 + 1] = o_acc[nt][1] * il_lo;
        dst_hi[n0] = o_acc[nt][2] * il_hi; dst_hi[n0 + 1] = o_acc[nt][3] * il_hi;
    }
}

// ---------------------------------------------------------------------------
// Launch
// ---------------------------------------------------------------------------
extern "C" void kernel_launch(void* const* d_in, const int* in_sizes, int n_in,
                              void* d_out, int out_size)
{
    const float* x  = (const float*)d_in[0];
    const float* Wq = (const float*)d_in[1];
    const float* bq = (const float*)d_in[2];
    const float* Wk = (const float*)d_in[3];
    const float* bk = (const float*)d_in[4];
    const float* Wv = (const float*)d_in[5];
    const float* bv = (const float*)d_in[6];
    const float* Wo = (const float*)d_in[7];
    const float* bo = (const float*)d_in[8];
    float* out = (float*)d_out;

    float *pq, *pk, *pv, *pao;
    cudaGetSymbolAddress((void**)&pq,  g_q);
    cudaGetSymbolAddress((void**)&pk,  g_k);
    cudaGetSymbolAddress((void**)&pv,  g_v);
    cudaGetSymbolAddress((void**)&pao, g_ao);

    dim3 gg(D_MODEL / 128, M_TOT / 128);   // (8, 64)
    gemm_tc<<<gg, 128>>>(x, Wq, bq, pq, 0);
    gemm_tc<<<gg, 128>>>(x, Wk, bk, pk, 0);
    gemm_tc<<<gg, 128>>>(x, Wv, bv, pv, 0);

    size_t smem = (size_t)(128 * KSTR) * sizeof(__half);  // 18,432 B (Q staging max)
    attn_tc<<<dim3(SEQ / BQ, BATCH * NH), 256, smem>>>(pq, pk, pv, pao);

    gemm_tc<<<gg, 128>>>(pao, Wo, bo, out, 1);
}

// round 6
// speedup vs baseline: 7.9881x; 1.4177x over previous
#include <cuda_runtime.h>
#include <cuda_fp16.h>

#define D_MODEL 1024
#define NH 16
#define DK 64
#define BATCH 4
#define SEQ 2048
#define M_TOT (BATCH * SEQ)   // 8192

#define SCALE_Q 0.18033688011112042f   // 0.125 * log2(e)

// ---------------------------------------------------------------------------
// Scratch (device globals; allocation is forbidden)
// ---------------------------------------------------------------------------
__device__ __half g_xh [(size_t)M_TOT * D_MODEL];
__device__ __half g_wqt[(size_t)D_MODEL * D_MODEL];
__device__ __half g_wkt[(size_t)D_MODEL * D_MODEL];
__device__ __half g_wvt[(size_t)D_MODEL * D_MODEL];
__device__ __half g_wot[(size_t)D_MODEL * D_MODEL];
__device__ __half g_qh [(size_t)M_TOT * D_MODEL];   // [b,h,s,dk] (pre-scaled)
__device__ __half g_kh [(size_t)M_TOT * D_MODEL];   // [b,h,s,dk]
__device__ __half g_vh [(size_t)M_TOT * D_MODEL];   // [b,h,s,dk]
__device__ __half g_aoh[(size_t)M_TOT * D_MODEL];   // [b,s,h*dk]

// ---------------------------------------------------------------------------
// helpers
// ---------------------------------------------------------------------------
__device__ __forceinline__ unsigned packh2(float lo, float hi) {
    __half2 h = __floats2half2_rn(lo, hi);
    return *(unsigned*)&h;
}

__device__ __forceinline__ void mma16h(float c[4],
    unsigned a0, unsigned a1, unsigned a2, unsigned a3,
    unsigned b0, unsigned b1)
{
    asm volatile(
        "mma.sync.aligned.m16n8k16.row.col.f32.f16.f16.f32 "
        "{%0,%1,%2,%3}, {%4,%5,%6,%7}, {%8,%9}, {%0,%1,%2,%3};\n"
        : "+f"(c[0]), "+f"(c[1]), "+f"(c[2]), "+f"(c[3])
        : "r"(a0), "r"(a1), "r"(a2), "r"(a3), "r"(b0), "r"(b1));
}

__device__ __forceinline__ void ldsm4(unsigned& r0, unsigned& r1,
                                      unsigned& r2, unsigned& r3, unsigned addr)
{
    asm volatile("ldmatrix.sync.aligned.m8n8.x4.shared.b16 {%0,%1,%2,%3}, [%4];\n"
        : "=r"(r0), "=r"(r1), "=r"(r2), "=r"(r3) : "r"(addr));
}

__device__ __forceinline__ void ldsm4t(unsigned& r0, unsigned& r1,
                                       unsigned& r2, unsigned& r3, unsigned addr)
{
    asm volatile("ldmatrix.sync.aligned.m8n8.x4.trans.shared.b16 {%0,%1,%2,%3}, [%4];\n"
        : "=r"(r0), "=r"(r1), "=r"(r2), "=r"(r3) : "r"(addr));
}

#define CP16(dst, src) \
    asm volatile("cp.async.cg.shared.global [%0], [%1], 16;\n" :: "r"(dst), "l"(src))
#define CP_COMMIT() asm volatile("cp.async.commit_group;\n")
#define CP_WAIT(n)  asm volatile("cp.async.wait_group %0;\n" :: "n"(n))

// ---------------------------------------------------------------------------
// Pre-conversion kernels
// ---------------------------------------------------------------------------
__global__ void f2h_kernel(const float* __restrict__ in, __half* __restrict__ out)
{
    int i = blockIdx.x * blockDim.x + threadIdx.x;
    float4 t = ((const float4*)in)[i];
    ((uint2*)out)[i] = make_uint2(packh2(t.x, t.y), packh2(t.z, t.w));
}

__global__ void transw_kernel(const float* __restrict__ W, __half* __restrict__ Wt)
{
    __shared__ float tile[32][33];
    int k0 = blockIdx.x * 32, n0 = blockIdx.y * 32;
    int tx = threadIdx.x, ty = threadIdx.y;   // (32, 8)
#pragma unroll
    for (int j = 0; j < 4; j++)
        tile[ty * 4 + j][tx] = W[(size_t)(k0 + ty * 4 + j) * D_MODEL + n0 + tx];
    __syncthreads();
#pragma unroll
    for (int j = 0; j < 4; j++)
        Wt[(size_t)(n0 + ty * 4 + j) * D_MODEL + k0 + tx] =
            __float2half(tile[tx][ty * 4 + j]);
}

// ---------------------------------------------------------------------------
// fp16 GEMM with 3-stage cp.async pipeline.
// C[8192,1024] = A_h[8192,1024] @ Wt_h[1024,1024]^T(+bias)
// BM=128, BN=128, BK=32, 128 threads (4 warps of 64x64 warp tiles).
// mode 0: fp16 scatter into [b,h,s,dk] with (acc+bias)*scale.
// mode 1: fp32 row-major + bias.
// ---------------------------------------------------------------------------
#define GAS 40   // half stride (32 + 8 pad); row stride 80B

__global__ __launch_bounds__(128, 2) void gemm_h(
    const __half* __restrict__ A, const __half* __restrict__ Wt,
    const float* __restrict__ bias, void* __restrict__ outp,
    int mode, float scale)
{
    extern __shared__ __half gsm[];   // 3 stages x (A 128*GAS + B 128*GAS)

    const int tid  = threadIdx.x;
    const int lane = tid & 31;
    const int wid  = tid >> 5;
    const int g    = lane >> 2;
    const int qd   = lane & 3;
    const int wm   = (wid >> 1) * 64;
    const int wn   = (wid & 1) * 64;
    const int bm   = blockIdx.y * 128;
    const int bn   = blockIdx.x * 128;

    const unsigned sm_u = (unsigned)__cvta_generic_to_shared(gsm);

    const unsigned a_row = (lane & 15);
    const unsigned a_col = (lane >> 4) * 8;
    const unsigned b_n   = (lane & 7) + ((lane >> 4) & 1) * 8;
    const unsigned b_k   = ((lane >> 3) & 1) * 8;

    float c[4][8][4];
#pragma unroll
    for (int mt = 0; mt < 4; mt++)
#pragma unroll
        for (int nt = 0; nt < 8; nt++)
#pragma unroll
            for (int i = 0; i < 4; i++) c[mt][nt][i] = 0.f;

    // per-thread load coords: chunk c = tid + i*128 -> r = c>>2, k8 = (c&3)*8
    const int lr  = tid >> 2;
    const int lk8 = (tid & 3) * 8;

    auto issue = [&](int kit, int st) {
        unsigned abase = sm_u + (unsigned)(st * 2 * 128 * GAS) * 2;
        unsigned bbase = abase + (unsigned)(128 * GAS) * 2;
#pragma unroll
        for (int i = 0; i < 4; i++) {
            int r = lr + i * 32;
            CP16(abase + (r * GAS + lk8) * 2, A  + (size_t)(bm + r) * D_MODEL + kit * 32 + lk8);
            CP16(bbase + (r * GAS + lk8) * 2, Wt + (size_t)(bn + r) * D_MODEL + kit * 32 + lk8);
        }
    };

    issue(0, 0); CP_COMMIT();
    issue(1, 1); CP_COMMIT();

    const int KI = D_MODEL / 32;   // 32
    for (int kit = 0; kit < KI; kit++) {
        CP_WAIT(1);
        __syncthreads();
        if (kit + 2 < KI) issue(kit + 2, (kit + 2) % 3);
        CP_COMMIT();

        int st = kit % 3;
        unsigned abase = sm_u + (unsigned)(st * 2 * 128 * GAS) * 2;
        unsigned bbase = abase + (unsigned)(128 * GAS) * 2;
#pragma unroll
        for (int kk = 0; kk < 2; kk++) {
            unsigned a[4][4], b[4][4];
#pragma unroll
            for (int mt = 0; mt < 4; mt++) {
                unsigned addr = abase + ((wm + mt * 16 + a_row) * GAS + kk * 16 + a_col) * 2;
                ldsm4(a[mt][0], a[mt][1], a[mt][2], a[mt][3], addr);
            }
#pragma unroll
            for (int np = 0; np < 4; np++) {
                unsigned addr = bbase + ((wn + np * 16 + b_n) * GAS + kk * 16 + b_k) * 2;
                ldsm4(b[np][0], b[np][1], b[np][2], b[np][3], addr);
            }
#pragma unroll
            for (int mt = 0; mt < 4; mt++)
#pragma unroll
                for (int np = 0; np < 4; np++) {
                    mma16h(c[mt][2 * np],     a[mt][0], a[mt][1], a[mt][2], a[mt][3],
                           b[np][0], b[np][1]);
                    mma16h(c[mt][2 * np + 1], a[mt][0], a[mt][1], a[mt][2], a[mt][3],
                           b[np][2], b[np][3]);
                }
        }
    }

    // epilogue
#pragma unroll
    for (int mt = 0; mt < 4; mt++) {
        int r0 = bm + wm + mt * 16 + g;
        int r1 = r0 + 8;
#pragma unroll
        for (int nt = 0; nt < 8; nt++) {
            int n0 = bn + wn + nt * 8 + 2 * qd;
            float bb0 = bias[n0], bb1 = bias[n0 + 1];
            float v0 = c[mt][nt][0] + bb0, v1 = c[mt][nt][1] + bb1;
            float v2 = c[mt][nt][2] + bb0, v3 = c[mt][nt][3] + bb1;
            if (mode == 0) {
                int h = n0 >> 6, dd = n0 & 63;
                int b0_ = r0 >> 11, s0 = r0 & 2047;
                int b1_ = r1 >> 11, s1 = r1 & 2047;
                __half* out = (__half*)outp;
                *(__half2*)(out + (((size_t)(b0_ * NH + h)) * SEQ + s0) * DK + dd) =
                    __floats2half2_rn(v0 * scale, v1 * scale);
                *(__half2*)(out + (((size_t)(b1_ * NH + h)) * SEQ + s1) * DK + dd) =
                    __floats2half2_rn(v2 * scale, v3 * scale);
            } else {
                float* out = (float*)outp;
                float* p0 = out + (size_t)r0 * D_MODEL + n0;
                float* p1 = out + (size_t)r1 * D_MODEL + n0;
                p0[0] = v0; p0[1] = v1;
                p1[0] = v2; p1[1] = v3;
            }
        }
    }
}

// ---------------------------------------------------------------------------
// Flash attention, fp16 end-to-end, 3-stage cp.async K/V pipeline.
// BQ=128 queries, 128 threads = 4 warps x 32 q-rows (2 tiles of 16).
// Smem per stage: Ks[64][72] + Vs[64][72] halves (18,432 B); 3 stages.
// Q (pre-scaled by 0.125*log2e) staged in stage 0 region first.
// V consumed row-major via ldmatrix.trans. Softmax in exp2 domain.
// ---------------------------------------------------------------------------
#define BQ 128
#define KSTR 72

__global__ __launch_bounds__(128, 2) void attn_h(
    const __half* __restrict__ q, const __half* __restrict__ k,
    const __half* __restrict__ v, __half* __restrict__ o)
{
    extern __shared__ __half smh[];   // 3 * 9216 halves

    const int tid  = threadIdx.x;
    const int lane = tid & 31;
    const int wid  = tid >> 5;
    const int qd   = lane & 3;
    const int g    = lane >> 2;
    const int bh   = blockIdx.y;
    const int q0   = blockIdx.x * BQ;
    const int wrow = wid * 32;

    const unsigned sm_u = (unsigned)__cvta_generic_to_shared(smh);

    const unsigned a_row = (lane & 15);
    const unsigned a_col = (lane >> 4) * 8;
    const unsigned b_n   = (lane & 7) + ((lane >> 4) & 1) * 8;
    const unsigned b_k   = ((lane >> 3) & 1) * 8;
    // V trans-ldsm lane coords: k row + n col
    const unsigned vt_k  = (lane & 7) + ((lane >> 3) & 1) * 8;
    const unsigned vt_n  = (lane >> 4) * 8;

    const __half* Qg = q + ((size_t)bh * SEQ + q0) * DK;
    const __half* Kg = k + (size_t)bh * SEQ * DK;
    const __half* Vg = v + (size_t)bh * SEQ * DK;

    // ---- stage Q into stage-0 region via cp.async ----
    {
        const int lr  = tid >> 3;          // will add +16*i
        const int lk8 = (tid & 7) * 8;
#pragma unroll
        for (int i = 0; i < 8; i++) {
            int r = lr + i * 16;
            CP16(sm_u + (r * KSTR + lk8) * 2, Qg + (size_t)r * DK + lk8);
        }
    }
    CP_COMMIT();
    CP_WAIT(0);
    __syncthreads();

    unsigned qf[2][4][4];
#pragma unroll
    for (int mt = 0; mt < 2; mt++)
#pragma unroll
        for (int kk = 0; kk < 4; kk++) {
            unsigned addr = sm_u + ((wrow + mt * 16 + a_row) * KSTR + kk * 16 + a_col) * 2;
            ldsm4(qf[mt][kk][0], qf[mt][kk][1], qf[mt][kk][2], qf[mt][kk][3], addr);
        }
    __syncthreads();   // all qf reads done before stage 0 is overwritten

    // per-thread K/V load coords
    const int lr  = tid >> 3;   // 0..15, +16*i
    const int lk8 = (tid & 7) * 8;

    auto issue = [&](int kt, int st) {
        unsigned kbase = sm_u + (unsigned)(st * 2 * 64 * KSTR) * 2;
        unsigned vbase = kbase + (unsigned)(64 * KSTR) * 2;
#pragma unroll
        for (int i = 0; i < 4; i++) {
            int r = lr + i * 16;
            CP16(kbase + (r * KSTR + lk8) * 2, Kg + (size_t)(kt * 64 + r) * DK + lk8);
            CP16(vbase + (r * KSTR + lk8) * 2, Vg + (size_t)(kt * 64 + r) * DK + lk8);
        }
    };

    issue(0, 0); CP_COMMIT();
    issue(1, 1); CP_COMMIT();

    float o_acc[2][8][4];
#pragma unroll
    for (int mt = 0; mt < 2; mt++)
#pragma unroll
        for (int nt = 0; nt < 8; nt++)
#pragma unroll
            for (int i = 0; i < 4; i++) o_acc[mt][nt][i] = 0.f;
    float m_r[2][2], l_r[2][2];
#pragma unroll
    for (int mt = 0; mt < 2; mt++) {
        m_r[mt][0] = -1e30f; m_r[mt][1] = -1e30f;
        l_r[mt][0] = 0.f;    l_r[mt][1] = 0.f;
    }

    const int NT = SEQ / 64;   // 32
    for (int kt = 0; kt < NT; kt++) {
        CP_WAIT(1);
        __syncthreads();
        if (kt + 2 < NT) issue(kt + 2, (kt + 2) % 3);
        CP_COMMIT();

        int st = kt % 3;
        unsigned kbase = sm_u + (unsigned)(st * 2 * 64 * KSTR) * 2;
        unsigned vbase = kbase + (unsigned)(64 * KSTR) * 2;

        // ---- S = Q @ K^T (log2e*0.125 folded into Q) ----
        float s[2][8][4];
#pragma unroll
        for (int mt = 0; mt < 2; mt++)
#pragma unroll
            for (int nt = 0; nt < 8; nt++)
#pragma unroll
                for (int i = 0; i < 4; i++) s[mt][nt][i] = 0.f;
#pragma unroll
        for (int kk = 0; kk < 4; kk++) {
#pragma unroll
            for (int np = 0; np < 4; np++) {
                unsigned b0, b1, b2, b3;
                unsigned addr = kbase + ((np * 16 + b_n) * KSTR + kk * 16 + b_k) * 2;
                ldsm4(b0, b1, b2, b3, addr);
#pragma unroll
                for (int mt = 0; mt < 2; mt++) {
                    mma16h(s[mt][2 * np],     qf[mt][kk][0], qf[mt][kk][1],
                           qf[mt][kk][2], qf[mt][kk][3], b0, b1);
                    mma16h(s[mt][2 * np + 1], qf[mt][kk][0], qf[mt][kk][1],
                           qf[mt][kk][2], qf[mt][kk][3], b2, b3);
                }
            }
        }

        // ---- online softmax (base-2) ----
#pragma unroll
        for (int mt = 0; mt < 2; mt++) {
            float mx_lo = -1e30f, mx_hi = -1e30f;
#pragma unroll
            for (int nt = 0; nt < 8; nt++) {
                mx_lo = fmaxf(mx_lo, fmaxf(s[mt][nt][0], s[mt][nt][1]));
                mx_hi = fmaxf(mx_hi, fmaxf(s[mt][nt][2], s[mt][nt][3]));
            }
            mx_lo = fmaxf(mx_lo, __shfl_xor_sync(0xffffffffu, mx_lo, 1));
            mx_lo = fmaxf(mx_lo, __shfl_xor_sync(0xffffffffu, mx_lo, 2));
            mx_hi = fmaxf(mx_hi, __shfl_xor_sync(0xffffffffu, mx_hi, 1));
            mx_hi = fmaxf(mx_hi, __shfl_xor_sync(0xffffffffu, mx_hi, 2));

            float mn_lo = fmaxf(m_r[mt][0], mx_lo), mn_hi = fmaxf(m_r[mt][1], mx_hi);
            float al_lo = exp2f(m_r[mt][0] - mn_lo), al_hi = exp2f(m_r[mt][1] - mn_hi);
            m_r[mt][0] = mn_lo; m_r[mt][1] = mn_hi;

            float sum_lo = 0.f, sum_hi = 0.f;
#pragma unroll
            for (int nt = 0; nt < 8; nt++) {
                float p0 = exp2f(s[mt][nt][0] - mn_lo);
                float p1 = exp2f(s[mt][nt][1] - mn_lo);
                float p2 = exp2f(s[mt][nt][2] - mn_hi);
                float p3 = exp2f(s[mt][nt][3] - mn_hi);
                sum_lo += p0 + p1; sum_hi += p2 + p3;
                s[mt][nt][0] = p0; s[mt][nt][1] = p1;
                s[mt][nt][2] = p2; s[mt][nt][3] = p3;
            }
            sum_lo += __shfl_xor_sync(0xffffffffu, sum_lo, 1);
            sum_lo += __shfl_xor_sync(0xffffffffu, sum_lo, 2);
            sum_hi += __shfl_xor_sync(0xffffffffu, sum_hi, 1);
            sum_hi += __shfl_xor_sync(0xffffffffu, sum_hi, 2);
            l_r[mt][0] = l_r[mt][0] * al_lo + sum_lo;
            l_r[mt][1] = l_r[mt][1] * al_hi + sum_hi;

#pragma unroll
            for (int nt = 0; nt < 8; nt++) {
                o_acc[mt][nt][0] *= al_lo; o_acc[mt][nt][1] *= al_lo;
                o_acc[mt][nt][2] *= al_hi; o_acc[mt][nt][3] *= al_hi;
            }
        }

        // ---- O += P @ V : A from packed P, B via ldmatrix.trans on row-major V ----
#pragma unroll
        for (int kk2 = 0; kk2 < 4; kk2++) {
            unsigned a[2][4];
#pragma unroll
            for (int mt = 0; mt < 2; mt++) {
                a[mt][0] = packh2(s[mt][2 * kk2][0],     s[mt][2 * kk2][1]);
                a[mt][1] = packh2(s[mt][2 * kk2][2],     s[mt][2 * kk2][3]);
                a[mt][2] = packh2(s[mt][2 * kk2 + 1][0], s[mt][2 * kk2 + 1][1]);
                a[mt][3] = packh2(s[mt][2 * kk2 + 1][2], s[mt][2 * kk2 + 1][3]);
            }
#pragma unroll
            for (int np = 0; np < 4; np++) {
                unsigned b0, b1, b2, b3;
                unsigned addr = vbase + ((kk2 * 16 + vt_k) * KSTR + np * 16 + vt_n) * 2;
                ldsm4t(b0, b1, b2, b3, addr);
#pragma unroll
                for (int mt = 0; mt < 2; mt++) {
                    mma16h(o_acc[mt][2 * np],     a[mt][0], a[mt][1], a[mt][2], a[mt][3],
                           b0, b1);
                    mma16h(o_acc[mt][2 * np + 1], a[mt][0], a[mt][1], a[mt][2], a[mt][3],
                           b2, b3);
                }
            }
        }
    }

    // ---- epilogue: normalize + write fp16 [b,s,h*dk] ----
    const int b_ = bh >> 4, h_ = bh & 15;
#pragma unroll
    for (int mt = 0; mt < 2; mt++) {
        float il_lo = 1.f / l_r[mt][0], il_hi = 1.f / l_r[mt][1];
        int s_lo = q0 + wrow + mt * 16 + g, s_hi = s_lo + 8;
        __half* dst_lo = o + ((size_t)(b_ * SEQ + s_lo)) * D_MODEL + h_ * DK;
        __half* dst_hi = o + ((size_t)(b_ * SEQ + s_hi)) * D_MODEL + h_ * DK;
#pragma unroll
        for (int nt = 0; nt < 8; nt++) {
            int n0 = nt * 8 + 2 * qd;
            *(__half2*)(dst_lo + n0) =
                __floats2half2_rn(o_acc[mt][nt][0] * il_lo, o_acc[mt][nt][1] * il_lo);
            *(__half2*)(dst_hi + n0) =
                __floats2half2_rn(o_acc[mt][nt][2] * il_hi, o_acc[mt][nt][3] * il_hi);
        }
    }
}

// ---------------------------------------------------------------------------
// Launch
// ---------------------------------------------------------------------------
extern "C" void kernel_launch(void* const* d_in, const int* in_sizes, int n_in,
                              void* d_out, int out_size)
{
    const float* x  = (const float*)d_in[0];
    const float* Wq = (const float*)d_in[1];
    const float* bq = (const float*)d_in[2];
    const float* Wk = (const float*)d_in[3];
    const float* bk = (const float*)d_in[4];
    const float* Wv = (const float*)d_in[5];
    const float* bv = (const float*)d_in[6];
    const float* Wo = (const float*)d_in[7];
    const float* bo = (const float*)d_in[8];
    float* out = (float*)d_out;

    __half *xh, *wqt, *wkt, *wvt, *wot, *qh, *kh, *vh, *aoh;
    cudaGetSymbolAddress((void**)&xh,  g_xh);
    cudaGetSymbolAddress((void**)&wqt, g_wqt);
    cudaGetSymbolAddress((void**)&wkt, g_wkt);
    cudaGetSymbolAddress((void**)&wvt, g_wvt);
    cudaGetSymbolAddress((void**)&wot, g_wot);
    cudaGetSymbolAddress((void**)&qh,  g_qh);
    cudaGetSymbolAddress((void**)&kh,  g_kh);
    cudaGetSymbolAddress((void**)&vh,  g_vh);
    cudaGetSymbolAddress((void**)&aoh, g_aoh);

    // conversions
    f2h_kernel<<<(M_TOT * D_MODEL / 4) / 256, 256>>>(x, xh);
    dim3 tw(32, 8), twg(D_MODEL / 32, D_MODEL / 32);
    transw_kernel<<<twg, tw>>>(Wq, wqt);
    transw_kernel<<<twg, tw>>>(Wk, wkt);
    transw_kernel<<<twg, tw>>>(Wv, wvt);
    transw_kernel<<<twg, tw>>>(Wo, wot);

    // GEMMs
    size_t gsm = (size_t)(3 * 2 * 128 * GAS) * sizeof(__half);   // 61,440 B
    cudaFuncSetAttribute(gemm_h, cudaFuncAttributeMaxDynamicSharedMemorySize, (int)gsm);
    dim3 gg(D_MODEL / 128, M_TOT / 128);   // (8, 64)
    gemm_h<<<gg, 128, gsm>>>(xh, wqt, bq, qh, 0, SCALE_Q);
    gemm_h<<<gg, 128, gsm>>>(xh, wkt, bk, kh, 0, 1.0f);
    gemm_h<<<gg, 128, gsm>>>(xh, wvt, bv, vh, 0, 1.0f);

    // attention
    size_t asm_ = (size_t)(3 * 2 * 64 * KSTR) * sizeof(__half);  // 55,296 B
    cudaFuncSetAttribute(attn_h, cudaFuncAttributeMaxDynamicSharedMemorySize, (int)asm_);
    attn_h<<<dim3(SEQ / BQ, BATCH * NH), 128, asm_>>>(qh, kh, vh, aoh);

    // output projection
    gemm_h<<<gg, 128, gsm>>>(aoh, wot, bo, out, 1, 1.0f);
}